// round 10
// baseline (speedup 1.0000x reference)
#include <cuda_runtime.h>
#include <cuda_bf16.h>
#include <cstdint>

// ---------------------------------------------------------------------------
// NRI decoder step. Edge+node MLPs on HMMA (mma.sync bf16 2-way split)
// Shapes: B=128, N=64, K=2, VDIM=EDIM=32, HID=64, E=4032, BE=516096
// Output: [dv (262144) | de (16515072) | zeros (1032192)] floats
// ---------------------------------------------------------------------------

#define BN_  128
#define NN_  64
#define EE_  4032
#define BE_  516096
#define DV_ELEMS   262144
#define ZERO_ELEMS 1032192
#define DE_OFF     262144
#define ZERO_OFF   16777216

using ull = unsigned long long;

// scratch (device globals; no runtime allocation)
__device__ float g_O[2 * 32 * BE_];          // edge MLP outputs [k*32+ch][ge]
__device__ float g_agg[BN_ * NN_ * 32];
__device__ float g_ov[BN_ * NN_ * 32];       // node MLP outputs [node][32]
__device__ float g_esum[64], g_esq[64];
__device__ float g_nsum[32], g_nsq[32];
// pre-split, pre-transposed weights (B-operand layout, k contiguous)
__device__ __nv_bfloat16 g_w1h[8192], g_w1l[8192];   // edge W1 [2][64 n][64 f]
__device__ __nv_bfloat16 g_w2h[4096], g_w2l[4096];   // edge W2 [2][32 n][64 h]
__device__ __nv_bfloat16 g_wv1h[2048], g_wv1l[2048]; // node W1 [64 n][32 f]
__device__ __nv_bfloat16 g_wv2h[2048], g_wv2l[2048]; // node W2 [32 n][64 h]

__device__ __forceinline__ float elu_f(float x) {
    return x > 0.f ? x : (__expf(x) - 1.f);
}
__device__ __forceinline__ uint32_t smem_u32(const void* p) {
    uint32_t a;
    asm("{ .reg .u64 t; cvta.to.shared.u64 t, %1; cvt.u32.u64 %0, t; }" : "=r"(a) : "l"(p));
    return a;
}
// fast 2-way bf16 split: h = bf16x2{lo=a,hi=b}; l = bf16x2 of residuals
__device__ __forceinline__ void split2(float a, float b, uint32_t& h, uint32_t& l) {
    uint32_t hh;
    asm("cvt.rn.bf16x2.f32 %0, %1, %2;" : "=r"(hh) : "f"(b), "f"(a));
    float fa = __uint_as_float(hh << 16);
    float fb = __uint_as_float(hh & 0xFFFF0000u);
    float ra = a - fa, rb = b - fb;
    uint32_t ll;
    asm("cvt.rn.bf16x2.f32 %0, %1, %2;" : "=r"(ll) : "f"(rb), "f"(ra));
    h = hh; l = ll;
}

// ---- warp MMA helpers ------------------------------------------------------
__device__ __forceinline__ void ldsm_x4(uint32_t addr, uint32_t r[4]) {
    asm volatile("ldmatrix.sync.aligned.m8n8.x4.shared.b16 {%0,%1,%2,%3}, [%4];"
        : "=r"(r[0]), "=r"(r[1]), "=r"(r[2]), "=r"(r[3]) : "r"(addr));
}
__device__ __forceinline__ void mma16816(float c[4], const uint32_t a[4], const uint32_t b[2]) {
    asm volatile("mma.sync.aligned.m16n8k16.row.col.f32.bf16.bf16.f32 "
        "{%0,%1,%2,%3}, {%4,%5,%6,%7}, {%8,%9}, {%0,%1,%2,%3};"
        : "+f"(c[0]), "+f"(c[1]), "+f"(c[2]), "+f"(c[3])
        : "r"(a[0]), "r"(a[1]), "r"(a[2]), "r"(a[3]), "r"(b[0]), "r"(b[1]));
}

// ---------------------------------------------------------------------------
// A) fused pre-pass: zeros+stats | weight prep (edge+node) | aggregation
//    grid = 4032 + 32 + 1024 = 5088 blocks x 256
// ---------------------------------------------------------------------------
__global__ __launch_bounds__(256) void prepass(
    const float* __restrict__ e0,
    const float* __restrict__ w1, const float* __restrict__ w2,
    const float* __restrict__ vw1, const float* __restrict__ vw2,
    float* __restrict__ zout)
{
    const int bx = blockIdx.x, tid = threadIdx.x;
    if (bx < 4032) {
        int idx = bx * 256 + tid;
        zout[idx] = 0.f;
        if (bx == 0) {
            if (tid < 64) { g_esum[tid] = 0.f; g_esq[tid] = 0.f; }
            else if (tid < 96) { g_nsum[tid - 64] = 0.f; g_nsq[tid - 64] = 0.f; }
        }
        return;
    }
    if (bx < 4064) {
        int t = (bx - 4032) * 256 + tid;        // 8192 threads
        {   // edge w1: t = (k*64+n)*64+f  <-  w1[(k*64+f)*64+n]
            int f = t & 63, n = (t >> 6) & 63, k = t >> 12;
            float v = w1[(k * 64 + f) * 64 + n];
            __nv_bfloat16 h = __float2bfloat16(v);
            g_w1h[t] = h;
            g_w1l[t] = __float2bfloat16(v - __bfloat162float(h));
        }
        if (t < 4096) {  // edge w2: t = (k*32+n)*64+h  <-  w2[(k*64+h)*32+n]
            int hh = t & 63, n = (t >> 6) & 31, k = t >> 11;
            float v = w2[(k * 64 + hh) * 32 + n];
            __nv_bfloat16 h = __float2bfloat16(v);
            g_w2h[t] = h;
            g_w2l[t] = __float2bfloat16(v - __bfloat162float(h));
        }
        if (t < 2048) {  // node w1: t = n*32+f  <-  vw1[f*64+n]
            int f = t & 31, n = t >> 5;
            float v = vw1[f * 64 + n];
            __nv_bfloat16 h = __float2bfloat16(v);
            g_wv1h[t] = h;
            g_wv1l[t] = __float2bfloat16(v - __bfloat162float(h));
        }
        if (t < 2048) {  // node w2: t = n*64+h  <-  vw2[h*32+n]
            int hh = t & 63, n = t >> 6;
            float v = vw2[hh * 32 + n];
            __nv_bfloat16 h = __float2bfloat16(v);
            g_wv2h[t] = h;
            g_wv2l[t] = __float2bfloat16(v - __bfloat162float(h));
        }
        return;
    }
    {   // edge2node aggregation
        int gw = ((bx - 4064) * 256 + tid) >> 5;
        int lane = tid & 31;
        int b = gw >> 6, j = gw & 63;
        const float* base = e0 + (size_t)b * (NN_ * 63 * 32) + lane;
        float acc = 0.f;
        #pragma unroll 4
        for (int i = 0; i < 64; ++i) {
            if (i == j) continue;
            int jj = (j < i) ? j : j - 1;
            acc += base[(i * 63 + jj) * 32];
        }
        g_agg[gw * 32 + lane] = acc * (1.f / 64.f);
    }
}

// ---------------------------------------------------------------------------
// B) unified HMMA kernel: blocks 0..4031 edge tiles, 4032..4095 node tiles
// smem (bytes):
//   0      X_H [128][72 b16] (phase A) / W1h (phase B)   18432
//   18432  X_L [128][72]                                 18432
//   36864  W1l                                           18432
//   55296  W2h [32 rows][72] (x2 k for edge)             9216
//   64512  W2l                                           9216
//   73728  CTRL: SB1[128] | SB2[64] | SSUM[64] | SSQ[64] 1280
// ---------------------------------------------------------------------------
#define XH_B   0
#define XL_B   18432
#define W1L_B  36864
#define W2H_B  55296
#define W2L_B  64512
#define CTRL_B 73728
#define EH_SMEM 75008

__global__ __launch_bounds__(128, 3) void mlp_hmma(
    const float* __restrict__ v0,
    const float* __restrict__ eb1, const float* __restrict__ eb2,
    const float* __restrict__ vb1, const float* __restrict__ vb2)
{
    extern __shared__ char sm[];
    const uint32_t smb = smem_u32(sm);
    const int tid = threadIdx.x, wid = tid >> 5, lid = tid & 31;
    const int R0 = wid * 32;

    float* SB1  = (float*)(sm + CTRL_B);
    float* SB2  = (float*)(sm + CTRL_B + 512);
    float* SSUM = (float*)(sm + CTRL_B + 768);
    float* SSQ  = (float*)(sm + CTRL_B + 1024);

    // lane-dependent address constants
    const int arow = (lid & 7) + ((lid >> 3) & 1) * 8;
    const int acol = (lid >> 4) * 16;
    const uint32_t aXh = smb + XH_B + (R0 + arow) * 144 + acol;
    const uint32_t aXl = smb + XL_B + (R0 + arow) * 144 + acol;
    // B-side x4 lane base: covers n16 per load
    const int b4off = (lid & 7) * 144 + ((lid >> 3) & 1) * 16 + ((lid >> 4) & 1) * 1152;
    const int g  = lid >> 2;
    const int cq = lid & 3;

    uint32_t* Xhw = (uint32_t*)(sm + XH_B);
    uint32_t* Xlw = (uint32_t*)(sm + XL_B);
    uint32_t* W1lw = (uint32_t*)(sm + W1L_B);
    uint32_t* W2hw = (uint32_t*)(sm + W2H_B);
    uint32_t* W2lw = (uint32_t*)(sm + W2L_B);

    if (blockIdx.x < 4032) {
        // ================= EDGE PATH =================
        const int ge = blockIdx.x * 128 + tid;
        const int b  = ge / EE_;
        const int e  = ge - b * EE_;
        const int i0 = e / 63, jj = e - i0 * 63;
        const int recv = (jj < i0) ? jj : jj + 1;
        const float4* vr = (const float4*)(v0 + (size_t)(b * 64 + recv) * 32);
        const float4* vs = (const float4*)(v0 + (size_t)(b * 64 + i0) * 32);
        #pragma unroll
        for (int c = 0; c < 16; ++c) {
            float4 f = (c < 8) ? vr[c] : vs[c - 8];
            uint32_t h0, l0, h1, l1;
            split2(f.x, f.y, h0, l0);
            split2(f.z, f.w, h1, l1);
            Xhw[tid * 36 + 2 * c]     = h0;
            Xhw[tid * 36 + 2 * c + 1] = h1;
            Xlw[tid * 36 + 2 * c]     = l0;
            Xlw[tid * 36 + 2 * c + 1] = l1;
        }
        {
            const uint32_t* gw1l = (const uint32_t*)g_w1l;
            const uint32_t* gw2h = (const uint32_t*)g_w2h;
            const uint32_t* gw2l = (const uint32_t*)g_w2l;
            for (int idx = tid; idx < 4096; idx += 128) {
                int w = idx & 31, n = (idx >> 5) & 63, kz = idx >> 11;
                W1lw[kz * 2304 + n * 36 + w] = gw1l[idx];
            }
            for (int idx = tid; idx < 2048; idx += 128) {
                int w = idx & 31, n = (idx >> 5) & 31, kz = idx >> 10;
                W2hw[kz * 1152 + n * 36 + w] = gw2h[idx];
                W2lw[kz * 1152 + n * 36 + w] = gw2l[idx];
            }
            if (tid < 128) SB1[tid] = eb1[tid];
            if (tid < 64)  { SB2[tid] = eb2[tid]; SSUM[tid] = 0.f; SSQ[tid] = 0.f; }
        }
        __syncthreads();

        uint32_t Ah[2][4][4];
        #pragma unroll
        for (int mt = 0; mt < 2; ++mt)
            #pragma unroll
            for (int kk = 0; kk < 4; ++kk)
                ldsm_x4(aXh + mt * 2304 + kk * 32, Ah[mt][kk]);
        __syncthreads();
        {
            const uint32_t* gw1h = (const uint32_t*)g_w1h;
            for (int idx = tid; idx < 4096; idx += 128) {
                int w = idx & 31, n = (idx >> 5) & 63, kz = idx >> 11;
                Xhw[kz * 2304 + n * 36 + w] = gw1h[idx];
            }
        }
        __syncthreads();

        const int geBase = blockIdx.x * 128;
        const uint32_t bW1h4 = smb + XH_B + b4off;
        const uint32_t bW1l4 = smb + W1L_B + b4off;
        const uint32_t bW2h4 = smb + W2H_B + b4off;
        const uint32_t bW2l4 = smb + W2L_B + b4off;

        #pragma unroll 1
        for (int k = 0; k < 2; ++k) {
            const float* SB1k = SB1 + k * 64;
            const float* SB2k = SB2 + k * 32;
            const uint32_t w1hk = bW1h4 + k * 9216;
            const uint32_t w1lk = bW1l4 + k * 9216;
            const uint32_t w2hk = bW2h4 + k * 4608;
            const uint32_t w2lk = bW2l4 + k * 4608;

            float acc[2][8][4];
            #pragma unroll
            for (int nt = 0; nt < 8; ++nt) {
                float bb0 = SB1k[nt * 8 + 2 * cq];
                float bb1 = SB1k[nt * 8 + 2 * cq + 1];
                acc[0][nt][0] = bb0; acc[0][nt][1] = bb1;
                acc[0][nt][2] = bb0; acc[0][nt][3] = bb1;
                acc[1][nt][0] = bb0; acc[1][nt][1] = bb1;
                acc[1][nt][2] = bb0; acc[1][nt][3] = bb1;
            }
            #pragma unroll
            for (int kk = 0; kk < 4; ++kk) {
                uint32_t Al0[4], Al1[4];
                ldsm_x4(aXl + kk * 32, Al0);
                ldsm_x4(aXl + 2304 + kk * 32, Al1);
                #pragma unroll
                for (int np = 0; np < 4; ++np) {
                    uint32_t bh[4], bl[4];
                    ldsm_x4(w1hk + np * 2304 + kk * 32, bh);
                    ldsm_x4(w1lk + np * 2304 + kk * 32, bl);
                    mma16816(acc[0][2*np],   Ah[0][kk], bh);
                    mma16816(acc[0][2*np+1], Ah[0][kk], bh + 2);
                    mma16816(acc[1][2*np],   Ah[1][kk], bh);
                    mma16816(acc[1][2*np+1], Ah[1][kk], bh + 2);
                    mma16816(acc[0][2*np],   Ah[0][kk], bl);
                    mma16816(acc[0][2*np+1], Ah[0][kk], bl + 2);
                    mma16816(acc[1][2*np],   Ah[1][kk], bl);
                    mma16816(acc[1][2*np+1], Ah[1][kk], bl + 2);
                    mma16816(acc[0][2*np],   Al0, bh);
                    mma16816(acc[0][2*np+1], Al0, bh + 2);
                    mma16816(acc[1][2*np],   Al1, bh);
                    mma16816(acc[1][2*np+1], Al1, bh + 2);
                }
            }

            uint32_t A2h[2][4][4], A2l[2][4][4];
            #pragma unroll
            for (int mt = 0; mt < 2; ++mt) {
                #pragma unroll
                for (int kk = 0; kk < 4; ++kk) {
                    float v00 = elu_f(acc[mt][2 * kk][0]);
                    float v01 = elu_f(acc[mt][2 * kk][1]);
                    float v10 = elu_f(acc[mt][2 * kk][2]);
                    float v11 = elu_f(acc[mt][2 * kk][3]);
                    float w00 = elu_f(acc[mt][2 * kk + 1][0]);
                    float w01 = elu_f(acc[mt][2 * kk + 1][1]);
                    float w10 = elu_f(acc[mt][2 * kk + 1][2]);
                    float w11 = elu_f(acc[mt][2 * kk + 1][3]);
                    split2(v00, v01, A2h[mt][kk][0], A2l[mt][kk][0]);
                    split2(v10, v11, A2h[mt][kk][1], A2l[mt][kk][1]);
                    split2(w00, w01, A2h[mt][kk][2], A2l[mt][kk][2]);
                    split2(w10, w11, A2h[mt][kk][3], A2l[mt][kk][3]);
                }
            }

            float ac2[2][4][4];
            #pragma unroll
            for (int nt = 0; nt < 4; ++nt) {
                float bb0 = SB2k[nt * 8 + 2 * cq];
                float bb1 = SB2k[nt * 8 + 2 * cq + 1];
                ac2[0][nt][0] = bb0; ac2[0][nt][1] = bb1;
                ac2[0][nt][2] = bb0; ac2[0][nt][3] = bb1;
                ac2[1][nt][0] = bb0; ac2[1][nt][1] = bb1;
                ac2[1][nt][2] = bb0; ac2[1][nt][3] = bb1;
            }
            #pragma unroll
            for (int kk = 0; kk < 4; ++kk) {
                #pragma unroll
                for (int np = 0; np < 2; ++np) {
                    uint32_t bh[4], bl[4];
                    ldsm_x4(w2hk + np * 2304 + kk * 32, bh);
                    ldsm_x4(w2lk + np * 2304 + kk * 32, bl);
                    mma16816(ac2[0][2*np],   A2h[0][kk], bh);
                    mma16816(ac2[0][2*np+1], A2h[0][kk], bh + 2);
                    mma16816(ac2[1][2*np],   A2h[1][kk], bh);
                    mma16816(ac2[1][2*np+1], A2h[1][kk], bh + 2);
                    mma16816(ac2[0][2*np],   A2h[0][kk], bl);
                    mma16816(ac2[0][2*np+1], A2h[0][kk], bl + 2);
                    mma16816(ac2[1][2*np],   A2h[1][kk], bl);
                    mma16816(ac2[1][2*np+1], A2h[1][kk], bl + 2);
                    mma16816(ac2[0][2*np],   A2l[0][kk], bh);
                    mma16816(ac2[0][2*np+1], A2l[0][kk], bh + 2);
                    mma16816(ac2[1][2*np],   A2l[1][kk], bh);
                    mma16816(ac2[1][2*np+1], A2l[1][kk], bh + 2);
                }
            }

            float sl[8], ql[8];
            #pragma unroll
            for (int j = 0; j < 8; ++j) { sl[j] = 0.f; ql[j] = 0.f; }
            #pragma unroll
            for (int mt = 0; mt < 2; ++mt) {
                const int r0 = geBase + R0 + mt * 16 + g;
                #pragma unroll
                for (int nt = 0; nt < 4; ++nt) {
                    const int col = nt * 8 + 2 * cq;
                    float v00 = elu_f(ac2[mt][nt][0]);
                    float v01 = elu_f(ac2[mt][nt][1]);
                    float v10 = elu_f(ac2[mt][nt][2]);
                    float v11 = elu_f(ac2[mt][nt][3]);
                    g_O[(size_t)(k * 32 + col) * BE_ + r0]         = v00;
                    g_O[(size_t)(k * 32 + col + 1) * BE_ + r0]     = v01;
                    g_O[(size_t)(k * 32 + col) * BE_ + r0 + 8]     = v10;
                    g_O[(size_t)(k * 32 + col + 1) * BE_ + r0 + 8] = v11;
                    sl[nt * 2]     += v00 + v10;
                    ql[nt * 2]     += v00 * v00 + v10 * v10;
                    sl[nt * 2 + 1] += v01 + v11;
                    ql[nt * 2 + 1] += v01 * v01 + v11 * v11;
                }
            }
            #pragma unroll
            for (int j = 0; j < 8; ++j) {
                #pragma unroll
                for (int off = 4; off < 32; off <<= 1) {
                    sl[j] += __shfl_xor_sync(0xffffffffu, sl[j], off);
                    ql[j] += __shfl_xor_sync(0xffffffffu, ql[j], off);
                }
            }
            if (lid < 4) {
                #pragma unroll
                for (int nt = 0; nt < 4; ++nt) {
                    atomicAdd(&SSUM[k * 32 + nt * 8 + 2 * lid],     sl[nt * 2]);
                    atomicAdd(&SSQ [k * 32 + nt * 8 + 2 * lid],     ql[nt * 2]);
                    atomicAdd(&SSUM[k * 32 + nt * 8 + 2 * lid + 1], sl[nt * 2 + 1]);
                    atomicAdd(&SSQ [k * 32 + nt * 8 + 2 * lid + 1], ql[nt * 2 + 1]);
                }
            }
        }
        __syncthreads();
        if (tid < 64) { atomicAdd(&g_esum[tid], SSUM[tid]); atomicAdd(&g_esq[tid], SSQ[tid]); }
    } else {
        // ================= NODE PATH =================
        const int nb = (blockIdx.x - 4032) * 128;
        {
            const float4* ar = (const float4*)(g_agg + (size_t)(nb + tid) * 32);
            #pragma unroll
            for (int c = 0; c < 8; ++c) {
                float4 f = ar[c];
                uint32_t h0, l0, h1, l1;
                split2(f.x, f.y, h0, l0);
                split2(f.z, f.w, h1, l1);
                Xhw[tid * 36 + 2 * c]     = h0;
                Xhw[tid * 36 + 2 * c + 1] = h1;
                Xlw[tid * 36 + 2 * c]     = l0;
                Xlw[tid * 36 + 2 * c + 1] = l1;
            }
            const uint32_t* gv1l = (const uint32_t*)g_wv1l;
            const uint32_t* gv2h = (const uint32_t*)g_wv2h;
            const uint32_t* gv2l = (const uint32_t*)g_wv2l;
            for (int idx = tid; idx < 1024; idx += 128) {   // node W1: [64n][16w]
                int w = idx & 15, n = idx >> 4;
                W1lw[n * 36 + w] = gv1l[idx];
            }
            for (int idx = tid; idx < 2048; idx += 128) {   // node W2: [32n][32w]
                int w = idx & 31, n = idx >> 5;
                W2hw[n * 36 + w] = gv2h[idx];
                W2lw[n * 36 + w] = gv2l[idx];
            }
            if (tid < 64) { SB1[tid] = vb1[tid]; SSUM[tid] = 0.f; SSQ[tid] = 0.f; }
            if (tid < 32) SB2[tid] = vb2[tid];
        }
        __syncthreads();

        uint32_t Ah[2][2][4];
        #pragma unroll
        for (int mt = 0; mt < 2; ++mt)
            #pragma unroll
            for (int kk = 0; kk < 2; ++kk)
                ldsm_x4(aXh + mt * 2304 + kk * 32, Ah[mt][kk]);
        __syncthreads();
        {
            const uint32_t* gv1h = (const uint32_t*)g_wv1h;
            for (int idx = tid; idx < 1024; idx += 128) {
                int w = idx & 15, n = idx >> 4;
                Xhw[n * 36 + w] = gv1h[idx];
            }
        }
        __syncthreads();

        const uint32_t w1hk = smb + XH_B + b4off;
        const uint32_t w1lk = smb + W1L_B + b4off;
        const uint32_t w2hk = smb + W2H_B + b4off;
        const uint32_t w2lk = smb + W2L_B + b4off;

        float acc[2][8][4];
        #pragma unroll
        for (int nt = 0; nt < 8; ++nt) {
            float bb0 = SB1[nt * 8 + 2 * cq];
            float bb1 = SB1[nt * 8 + 2 * cq + 1];
            acc[0][nt][0] = bb0; acc[0][nt][1] = bb1;
            acc[0][nt][2] = bb0; acc[0][nt][3] = bb1;
            acc[1][nt][0] = bb0; acc[1][nt][1] = bb1;
            acc[1][nt][2] = bb0; acc[1][nt][3] = bb1;
        }
        #pragma unroll
        for (int kk = 0; kk < 2; ++kk) {
            uint32_t Al0[4], Al1[4];
            ldsm_x4(aXl + kk * 32, Al0);
            ldsm_x4(aXl + 2304 + kk * 32, Al1);
            #pragma unroll
            for (int np = 0; np < 4; ++np) {
                uint32_t bh[4], bl[4];
                ldsm_x4(w1hk + np * 2304 + kk * 32, bh);
                ldsm_x4(w1lk + np * 2304 + kk * 32, bl);
                mma16816(acc[0][2*np],   Ah[0][kk], bh);
                mma16816(acc[0][2*np+1], Ah[0][kk], bh + 2);
                mma16816(acc[1][2*np],   Ah[1][kk], bh);
                mma16816(acc[1][2*np+1], Ah[1][kk], bh + 2);
                mma16816(acc[0][2*np],   Ah[0][kk], bl);
                mma16816(acc[0][2*np+1], Ah[0][kk], bl + 2);
                mma16816(acc[1][2*np],   Ah[1][kk], bl);
                mma16816(acc[1][2*np+1], Ah[1][kk], bl + 2);
                mma16816(acc[0][2*np],   Al0, bh);
                mma16816(acc[0][2*np+1], Al0, bh + 2);
                mma16816(acc[1][2*np],   Al1, bh);
                mma16816(acc[1][2*np+1], Al1, bh + 2);
            }
        }

        uint32_t A2h[2][4][4], A2l[2][4][4];
        #pragma unroll
        for (int mt = 0; mt < 2; ++mt) {
            #pragma unroll
            for (int kk = 0; kk < 4; ++kk) {
                float v00 = elu_f(acc[mt][2 * kk][0]);
                float v01 = elu_f(acc[mt][2 * kk][1]);
                float v10 = elu_f(acc[mt][2 * kk][2]);
                float v11 = elu_f(acc[mt][2 * kk][3]);
                float w00 = elu_f(acc[mt][2 * kk + 1][0]);
                float w01 = elu_f(acc[mt][2 * kk + 1][1]);
                float w10 = elu_f(acc[mt][2 * kk + 1][2]);
                float w11 = elu_f(acc[mt][2 * kk + 1][3]);
                split2(v00, v01, A2h[mt][kk][0], A2l[mt][kk][0]);
                split2(v10, v11, A2h[mt][kk][1], A2l[mt][kk][1]);
                split2(w00, w01, A2h[mt][kk][2], A2l[mt][kk][2]);
                split2(w10, w11, A2h[mt][kk][3], A2l[mt][kk][3]);
            }
        }

        float ac2[2][4][4];
        #pragma unroll
        for (int nt = 0; nt < 4; ++nt) {
            float bb0 = SB2[nt * 8 + 2 * cq];
            float bb1 = SB2[nt * 8 + 2 * cq + 1];
            ac2[0][nt][0] = bb0; ac2[0][nt][1] = bb1;
            ac2[0][nt][2] = bb0; ac2[0][nt][3] = bb1;
            ac2[1][nt][0] = bb0; ac2[1][nt][1] = bb1;
            ac2[1][nt][2] = bb0; ac2[1][nt][3] = bb1;
        }
        #pragma unroll
        for (int kk = 0; kk < 4; ++kk) {
            #pragma unroll
            for (int np = 0; np < 2; ++np) {
                uint32_t bh[4], bl[4];
                ldsm_x4(w2hk + np * 2304 + kk * 32, bh);
                ldsm_x4(w2lk + np * 2304 + kk * 32, bl);
                mma16816(ac2[0][2*np],   A2h[0][kk], bh);
                mma16816(ac2[0][2*np+1], A2h[0][kk], bh + 2);
                mma16816(ac2[1][2*np],   A2h[1][kk], bh);
                mma16816(ac2[1][2*np+1], A2h[1][kk], bh + 2);
                mma16816(ac2[0][2*np],   A2h[0][kk], bl);
                mma16816(ac2[0][2*np+1], A2h[0][kk], bl + 2);
                mma16816(ac2[1][2*np],   A2h[1][kk], bl);
                mma16816(ac2[1][2*np+1], A2h[1][kk], bl + 2);
                mma16816(ac2[0][2*np],   A2l[0][kk], bh);
                mma16816(ac2[0][2*np+1], A2l[0][kk], bh + 2);
                mma16816(ac2[1][2*np],   A2l[1][kk], bh);
                mma16816(ac2[1][2*np+1], A2l[1][kk], bh + 2);
            }
        }

        float sl[8], ql[8];
        #pragma unroll
        for (int j = 0; j < 8; ++j) { sl[j] = 0.f; ql[j] = 0.f; }
        #pragma unroll
        for (int mt = 0; mt < 2; ++mt) {
            const int n0 = nb + R0 + mt * 16 + g;
            #pragma unroll
            for (int nt = 0; nt < 4; ++nt) {
                const int col = nt * 8 + 2 * cq;
                float v00 = elu_f(ac2[mt][nt][0]);
                float v01 = elu_f(ac2[mt][nt][1]);
                float v10 = elu_f(ac2[mt][nt][2]);
                float v11 = elu_f(ac2[mt][nt][3]);
                *(float2*)(g_ov + (size_t)n0 * 32 + col)       = make_float2(v00, v01);
                *(float2*)(g_ov + (size_t)(n0 + 8) * 32 + col) = make_float2(v10, v11);
                sl[nt * 2]     += v00 + v10;
                ql[nt * 2]     += v00 * v00 + v10 * v10;
                sl[nt * 2 + 1] += v01 + v11;
                ql[nt * 2 + 1] += v01 * v01 + v11 * v11;
            }
        }
        #pragma unroll
        for (int j = 0; j < 8; ++j) {
            #pragma unroll
            for (int off = 4; off < 32; off <<= 1) {
                sl[j] += __shfl_xor_sync(0xffffffffu, sl[j], off);
                ql[j] += __shfl_xor_sync(0xffffffffu, ql[j], off);
            }
        }
        if (lid < 4) {
            #pragma unroll
            for (int nt = 0; nt < 4; ++nt) {
                atomicAdd(&SSUM[nt * 8 + 2 * lid],     sl[nt * 2]);
                atomicAdd(&SSQ [nt * 8 + 2 * lid],     ql[nt * 2]);
                atomicAdd(&SSUM[nt * 8 + 2 * lid + 1], sl[nt * 2 + 1]);
                atomicAdd(&SSQ [nt * 8 + 2 * lid + 1], ql[nt * 2 + 1]);
            }
        }
        __syncthreads();
        if (tid < 32) { atomicAdd(&g_nsum[tid], SSUM[tid]); atomicAdd(&g_nsq[tid], SSQ[tid]); }
    }
}

// ---------------------------------------------------------------------------
// C) fused post-pass: node_norm (blocks 0..1023) | edge_out (1024..3039)
//    edge part: register accumulation, direct contiguous float4 stores
// ---------------------------------------------------------------------------
__global__ __launch_bounds__(256) void postpass(
    const float* __restrict__ et,
    const float* __restrict__ eg, const float* __restrict__ ebet,
    const float* __restrict__ vg, const float* __restrict__ vbet,
    float* __restrict__ dv, float* __restrict__ de)
{
    __shared__ float A[64], C[64];
    const int bx = blockIdx.x, tid = threadIdx.x;

    if (bx < 1024) {
        if (tid < 32) {
            const float inv_cnt = 1.f / 8192.f;
            float mu = g_nsum[tid] * inv_cnt;
            float var = g_nsq[tid] * inv_cnt - mu * mu;
            float a = vg[tid] * rsqrtf(var + 1e-5f);
            A[tid] = a; C[tid] = vbet[tid] - mu * a;
        }
        __syncthreads();
        int idx = bx * 256 + tid;
        int c = idx & 31;
        dv[idx] = g_ov[idx] * A[c] + C[c];
        return;
    }

    if (tid < 64) {
        const float inv_cnt = 1.f / (float)BE_;
        float mu = g_esum[tid] * inv_cnt;
        float var = g_esq[tid] * inv_cnt - mu * mu;
        float a = eg[tid] * rsqrtf(var + 1e-5f);
        A[tid] = a; C[tid] = ebet[tid] - mu * a;
    }
    __syncthreads();

    const int ge = (bx - 1024) * 256 + tid;
    const float2 w = reinterpret_cast<const float2*>(et)[ge];
    float4* dst = (float4*)(de + (size_t)ge * 32);
    #pragma unroll
    for (int i = 0; i < 8; ++i) {
        float4 o;
        #pragma unroll
        for (int j = 0; j < 4; ++j) {
            const int c = 4 * i + j;
            float x0 = g_O[(size_t)c * BE_ + ge];
            float x1 = g_O[(size_t)(32 + c) * BE_ + ge];
            float r = (A[c] * x0 + C[c]) * w.x + (A[32 + c] * x1 + C[32 + c]) * w.y;
            (&o.x)[j] = r;
        }
        dst[i] = o;
    }
}

// ---------------------------------------------------------------------------
extern "C" void kernel_launch(void* const* d_in, const int* in_sizes, int n_in,
                              void* d_out, int out_size)
{
    const float* v0   = (const float*)d_in[0];
    const float* e0   = (const float*)d_in[1];
    const float* et   = (const float*)d_in[2];
    const float* vW1  = (const float*)d_in[3];
    const float* vb1  = (const float*)d_in[4];
    const float* vW2  = (const float*)d_in[5];
    const float* vb2  = (const float*)d_in[6];
    const float* vg   = (const float*)d_in[7];
    const float* vbet = (const float*)d_in[8];
    const float* eW1  = (const float*)d_in[9];
    const float* eb1  = (const float*)d_in[10];
    const float* eW2  = (const float*)d_in[11];
    const float* eb2  = (const float*)d_in[12];
    const float* eg   = (const float*)d_in[13];
    const float* ebet = (const float*)d_in[14];
    float* out = (float*)d_out;

    cudaFuncSetAttribute(mlp_hmma, cudaFuncAttributeMaxDynamicSharedMemorySize, EH_SMEM);
    cudaFuncSetAttribute(mlp_hmma, cudaFuncAttributePreferredSharedMemoryCarveout, 100);

    prepass<<<5088, 256>>>(e0, eW1, eW2, vW1, vW2, out + ZERO_OFF);
    mlp_hmma<<<4096, 128, EH_SMEM>>>(v0, eb1, eb2, vb1, vb2);
    postpass<<<3040, 256>>>(et, eg, ebet, vg, vbet, out, out + DE_OFF);

    (void)in_sizes; (void)n_in; (void)out_size;
}

// round 11
// speedup vs baseline: 1.1027x; 1.1027x over previous
#include <cuda_runtime.h>
#include <cuda_bf16.h>
#include <cstdint>

// ---------------------------------------------------------------------------
// NRI decoder step. Edge+node MLPs on HMMA (mma.sync bf16 2-way split)
// A-operand fragments gathered once into registers straight from global.
// Shapes: B=128, N=64, K=2, VDIM=EDIM=32, HID=64, E=4032, BE=516096
// Output: [dv (262144) | de (16515072) | zeros (1032192)] floats
// ---------------------------------------------------------------------------

#define BN_  128
#define NN_  64
#define EE_  4032
#define BE_  516096
#define DV_ELEMS   262144
#define ZERO_ELEMS 1032192
#define DE_OFF     262144
#define ZERO_OFF   16777216

using ull = unsigned long long;

// scratch (device globals; no runtime allocation)
__device__ float g_O[2 * 32 * BE_];          // edge MLP outputs [k*32+ch][ge]
__device__ float g_agg[BN_ * NN_ * 32];
__device__ float g_ov[BN_ * NN_ * 32];       // node MLP outputs [node][32]
__device__ float g_esum[64], g_esq[64];
__device__ float g_nsum[32], g_nsq[32];
// pre-split, pre-transposed weights (B-operand layout, k contiguous)
__device__ __nv_bfloat16 g_w1h[8192], g_w1l[8192];   // edge W1 [2][64 n][64 f]
__device__ __nv_bfloat16 g_w2h[4096], g_w2l[4096];   // edge W2 [2][32 n][64 h]
__device__ __nv_bfloat16 g_wv1h[2048], g_wv1l[2048]; // node W1 [64 n][32 f]
__device__ __nv_bfloat16 g_wv2h[2048], g_wv2l[2048]; // node W2 [32 n][64 h]

__device__ __forceinline__ float elu_f(float x) {
    return x > 0.f ? x : (__expf(x) - 1.f);
}
__device__ __forceinline__ uint32_t smem_u32(const void* p) {
    uint32_t a;
    asm("{ .reg .u64 t; cvta.to.shared.u64 t, %1; cvt.u32.u64 %0, t; }" : "=r"(a) : "l"(p));
    return a;
}
// fast 2-way bf16 split: h = bf16x2{lo=a,hi=b}; l = bf16x2 of residuals
__device__ __forceinline__ void split2(float a, float b, uint32_t& h, uint32_t& l) {
    uint32_t hh;
    asm("cvt.rn.bf16x2.f32 %0, %1, %2;" : "=r"(hh) : "f"(b), "f"(a));
    float fa = __uint_as_float(hh << 16);
    float fb = __uint_as_float(hh & 0xFFFF0000u);
    float ra = a - fa, rb = b - fb;
    uint32_t ll;
    asm("cvt.rn.bf16x2.f32 %0, %1, %2;" : "=r"(ll) : "f"(rb), "f"(ra));
    h = hh; l = ll;
}

// ---- warp MMA helpers ------------------------------------------------------
__device__ __forceinline__ void ldsm_x4(uint32_t addr, uint32_t r[4]) {
    asm volatile("ldmatrix.sync.aligned.m8n8.x4.shared.b16 {%0,%1,%2,%3}, [%4];"
        : "=r"(r[0]), "=r"(r[1]), "=r"(r[2]), "=r"(r[3]) : "r"(addr));
}
__device__ __forceinline__ void mma16816(float c[4], const uint32_t a[4], const uint32_t b[2]) {
    asm volatile("mma.sync.aligned.m16n8k16.row.col.f32.bf16.bf16.f32 "
        "{%0,%1,%2,%3}, {%4,%5,%6,%7}, {%8,%9}, {%0,%1,%2,%3};"
        : "+f"(c[0]), "+f"(c[1]), "+f"(c[2]), "+f"(c[3])
        : "r"(a[0]), "r"(a[1]), "r"(a[2]), "r"(a[3]), "r"(b[0]), "r"(b[1]));
}

// ---------------------------------------------------------------------------
// A) fused pre-pass: zeros+stats | weight prep (edge+node) | aggregation
// ---------------------------------------------------------------------------
__global__ __launch_bounds__(256) void prepass(
    const float* __restrict__ e0,
    const float* __restrict__ w1, const float* __restrict__ w2,
    const float* __restrict__ vw1, const float* __restrict__ vw2,
    float* __restrict__ zout)
{
    const int bx = blockIdx.x, tid = threadIdx.x;
    if (bx < 4032) {
        int idx = bx * 256 + tid;
        zout[idx] = 0.f;
        if (bx == 0) {
            if (tid < 64) { g_esum[tid] = 0.f; g_esq[tid] = 0.f; }
            else if (tid < 96) { g_nsum[tid - 64] = 0.f; g_nsq[tid - 64] = 0.f; }
        }
        return;
    }
    if (bx < 4064) {
        int t = (bx - 4032) * 256 + tid;        // 8192 threads
        {   // edge w1: t = (k*64+n)*64+f  <-  w1[(k*64+f)*64+n]
            int f = t & 63, n = (t >> 6) & 63, k = t >> 12;
            float v = w1[(k * 64 + f) * 64 + n];
            __nv_bfloat16 h = __float2bfloat16(v);
            g_w1h[t] = h;
            g_w1l[t] = __float2bfloat16(v - __bfloat162float(h));
        }
        if (t < 4096) {  // edge w2
            int hh = t & 63, n = (t >> 6) & 31, k = t >> 11;
            float v = w2[(k * 64 + hh) * 32 + n];
            __nv_bfloat16 h = __float2bfloat16(v);
            g_w2h[t] = h;
            g_w2l[t] = __float2bfloat16(v - __bfloat162float(h));
        }
        if (t < 2048) {  // node w1: t = n*32+f  <-  vw1[f*64+n]
            int f = t & 31, n = t >> 5;
            float v = vw1[f * 64 + n];
            __nv_bfloat16 h = __float2bfloat16(v);
            g_wv1h[t] = h;
            g_wv1l[t] = __float2bfloat16(v - __bfloat162float(h));
        }
        if (t < 2048) {  // node w2: t = n*64+h  <-  vw2[h*32+n]
            int hh = t & 63, n = t >> 6;
            float v = vw2[hh * 32 + n];
            __nv_bfloat16 h = __float2bfloat16(v);
            g_wv2h[t] = h;
            g_wv2l[t] = __float2bfloat16(v - __bfloat162float(h));
        }
        return;
    }
    {   // edge2node aggregation
        int gw = ((bx - 4064) * 256 + tid) >> 5;
        int lane = tid & 31;
        int b = gw >> 6, j = gw & 63;
        const float* base = e0 + (size_t)b * (NN_ * 63 * 32) + lane;
        float acc = 0.f;
        #pragma unroll 4
        for (int i = 0; i < 64; ++i) {
            if (i == j) continue;
            int jj = (j < i) ? j : j - 1;
            acc += base[(i * 63 + jj) * 32];
        }
        g_agg[gw * 32 + lane] = acc * (1.f / 64.f);
    }
}

// ---------------------------------------------------------------------------
// B) unified HMMA kernel: blocks 0..4031 edge tiles, 4032..4095 node tiles
//    No X smem: A fragments (hi+lo) gathered once into registers from global.
// smem (bytes):
//   0      W1h [2k][64 n][72 b16]   18432
//   18432  W1l                       18432
//   36864  W2h [2k][32 n][72]        9216
//   46080  W2l                       9216
//   55296  CTRL: SB1[128] SB2[64] SSUM[64] SSQ[64]  1280
// ---------------------------------------------------------------------------
#define W1H_B  0
#define W1L_B  18432
#define W2H_B  36864
#define W2L_B  46080
#define CTRL_B 55296
#define EH_SMEM 56576

__global__ __launch_bounds__(128, 3) void mlp_hmma(
    const float* __restrict__ v0,
    const float* __restrict__ eb1, const float* __restrict__ eb2,
    const float* __restrict__ vb1, const float* __restrict__ vb2)
{
    extern __shared__ char sm[];
    const uint32_t smb = smem_u32(sm);
    const int tid = threadIdx.x, wid = tid >> 5, lid = tid & 31;
    const int R0 = wid * 32;

    float* SB1  = (float*)(sm + CTRL_B);
    float* SB2  = (float*)(sm + CTRL_B + 512);
    float* SSUM = (float*)(sm + CTRL_B + 768);
    float* SSQ  = (float*)(sm + CTRL_B + 1024);

    // B-side x4 ldmatrix lane base (n16 x k16 per load)
    const int b4off = (lid & 7) * 144 + ((lid >> 3) & 1) * 16 + ((lid >> 4) & 1) * 1152;
    const int g  = lid >> 2;
    const int cq = lid & 3;

    uint32_t* W1hw = (uint32_t*)(sm + W1H_B);
    uint32_t* W1lw = (uint32_t*)(sm + W1L_B);
    uint32_t* W2hw = (uint32_t*)(sm + W2H_B);
    uint32_t* W2lw = (uint32_t*)(sm + W2L_B);

    if (blockIdx.x < 4032) {
        // ================= EDGE PATH =================
        // weight + bias loads (single phase, one barrier)
        {
            const uint32_t* gw1h = (const uint32_t*)g_w1h;
            const uint32_t* gw1l = (const uint32_t*)g_w1l;
            const uint32_t* gw2h = (const uint32_t*)g_w2h;
            const uint32_t* gw2l = (const uint32_t*)g_w2l;
            for (int idx = tid; idx < 4096; idx += 128) {
                int w = idx & 31, n = (idx >> 5) & 63, kz = idx >> 11;
                W1hw[kz * 2304 + n * 36 + w] = gw1h[idx];
                W1lw[kz * 2304 + n * 36 + w] = gw1l[idx];
            }
            for (int idx = tid; idx < 2048; idx += 128) {
                int w = idx & 31, n = (idx >> 5) & 31, kz = idx >> 10;
                W2hw[kz * 1152 + n * 36 + w] = gw2h[idx];
                W2lw[kz * 1152 + n * 36 + w] = gw2l[idx];
            }
            if (tid < 128) SB1[tid] = eb1[tid];
            if (tid < 64)  { SB2[tid] = eb2[tid]; SSUM[tid] = 0.f; SSQ[tid] = 0.f; }
        }

        // decode this lane's 4 edge rows
        const int geT = blockIdx.x * 128 + R0;
        int offR[4], offS[4];
        #pragma unroll
        for (int m2 = 0; m2 < 4; ++m2) {
            int mt = m2 >> 1, rs = (m2 & 1) * 8;
            int gid = geT + mt * 16 + g + rs;
            int b = gid / EE_;
            int e = gid - b * EE_;
            int i0 = e / 63, jj = e - i0 * 63;
            int rc = (jj < i0) ? jj : jj + 1;
            offR[m2] = (b * 64 + rc) * 32;
            offS[m2] = (b * 64 + i0) * 32;
        }

        // gather A fragments ONCE (hi + lo) from v0
        uint32_t Ah[2][4][4], Al[2][4][4];
        #pragma unroll
        for (int mt = 0; mt < 2; ++mt) {
            #pragma unroll
            for (int kk = 0; kk < 4; ++kk) {
                const int c0 = (kk & 1) * 16 + 2 * cq;
                const float* b0 = v0 + ((kk < 2) ? offR[mt * 2]     : offS[mt * 2]);
                const float* b1 = v0 + ((kk < 2) ? offR[mt * 2 + 1] : offS[mt * 2 + 1]);
                float2 f0 = *(const float2*)(b0 + c0);
                float2 f1 = *(const float2*)(b1 + c0);
                float2 f2 = *(const float2*)(b0 + c0 + 8);
                float2 f3 = *(const float2*)(b1 + c0 + 8);
                split2(f0.x, f0.y, Ah[mt][kk][0], Al[mt][kk][0]);
                split2(f1.x, f1.y, Ah[mt][kk][1], Al[mt][kk][1]);
                split2(f2.x, f2.y, Ah[mt][kk][2], Al[mt][kk][2]);
                split2(f3.x, f3.y, Ah[mt][kk][3], Al[mt][kk][3]);
            }
        }
        __syncthreads();

        const int geBase = blockIdx.x * 128;
        const uint32_t bW1h4 = smb + W1H_B + b4off;
        const uint32_t bW1l4 = smb + W1L_B + b4off;
        const uint32_t bW2h4 = smb + W2H_B + b4off;
        const uint32_t bW2l4 = smb + W2L_B + b4off;

        #pragma unroll 1
        for (int k = 0; k < 2; ++k) {
            const float* SB1k = SB1 + k * 64;
            const float* SB2k = SB2 + k * 32;
            const uint32_t w1hk = bW1h4 + k * 9216;
            const uint32_t w1lk = bW1l4 + k * 9216;
            const uint32_t w2hk = bW2h4 + k * 4608;
            const uint32_t w2lk = bW2l4 + k * 4608;

            float acc[2][8][4];
            #pragma unroll
            for (int nt = 0; nt < 8; ++nt) {
                float bb0 = SB1k[nt * 8 + 2 * cq];
                float bb1 = SB1k[nt * 8 + 2 * cq + 1];
                acc[0][nt][0] = bb0; acc[0][nt][1] = bb1;
                acc[0][nt][2] = bb0; acc[0][nt][3] = bb1;
                acc[1][nt][0] = bb0; acc[1][nt][1] = bb1;
                acc[1][nt][2] = bb0; acc[1][nt][3] = bb1;
            }
            #pragma unroll
            for (int kk = 0; kk < 4; ++kk) {
                #pragma unroll
                for (int np = 0; np < 4; ++np) {
                    uint32_t bh[4], bl[4];
                    ldsm_x4(w1hk + np * 2304 + kk * 32, bh);
                    ldsm_x4(w1lk + np * 2304 + kk * 32, bl);
                    mma16816(acc[0][2*np],   Ah[0][kk], bh);
                    mma16816(acc[0][2*np+1], Ah[0][kk], bh + 2);
                    mma16816(acc[1][2*np],   Ah[1][kk], bh);
                    mma16816(acc[1][2*np+1], Ah[1][kk], bh + 2);
                    mma16816(acc[0][2*np],   Ah[0][kk], bl);
                    mma16816(acc[0][2*np+1], Ah[0][kk], bl + 2);
                    mma16816(acc[1][2*np],   Ah[1][kk], bl);
                    mma16816(acc[1][2*np+1], Ah[1][kk], bl + 2);
                    mma16816(acc[0][2*np],   Al[0][kk], bh);
                    mma16816(acc[0][2*np+1], Al[0][kk], bh + 2);
                    mma16816(acc[1][2*np],   Al[1][kk], bh);
                    mma16816(acc[1][2*np+1], Al[1][kk], bh + 2);
                }
            }

            uint32_t A2h[2][4][4], A2l[2][4][4];
            #pragma unroll
            for (int mt = 0; mt < 2; ++mt) {
                #pragma unroll
                for (int kk = 0; kk < 4; ++kk) {
                    float v00 = elu_f(acc[mt][2 * kk][0]);
                    float v01 = elu_f(acc[mt][2 * kk][1]);
                    float v10 = elu_f(acc[mt][2 * kk][2]);
                    float v11 = elu_f(acc[mt][2 * kk][3]);
                    float w00 = elu_f(acc[mt][2 * kk + 1][0]);
                    float w01 = elu_f(acc[mt][2 * kk + 1][1]);
                    float w10 = elu_f(acc[mt][2 * kk + 1][2]);
                    float w11 = elu_f(acc[mt][2 * kk + 1][3]);
                    split2(v00, v01, A2h[mt][kk][0], A2l[mt][kk][0]);
                    split2(v10, v11, A2h[mt][kk][1], A2l[mt][kk][1]);
                    split2(w00, w01, A2h[mt][kk][2], A2l[mt][kk][2]);
                    split2(w10, w11, A2h[mt][kk][3], A2l[mt][kk][3]);
                }
            }

            float ac2[2][4][4];
            #pragma unroll
            for (int nt = 0; nt < 4; ++nt) {
                float bb0 = SB2k[nt * 8 + 2 * cq];
                float bb1 = SB2k[nt * 8 + 2 * cq + 1];
                ac2[0][nt][0] = bb0; ac2[0][nt][1] = bb1;
                ac2[0][nt][2] = bb0; ac2[0][nt][3] = bb1;
                ac2[1][nt][0] = bb0; ac2[1][nt][1] = bb1;
                ac2[1][nt][2] = bb0; ac2[1][nt][3] = bb1;
            }
            #pragma unroll
            for (int kk = 0; kk < 4; ++kk) {
                #pragma unroll
                for (int np = 0; np < 2; ++np) {
                    uint32_t bh[4], bl[4];
                    ldsm_x4(w2hk + np * 2304 + kk * 32, bh);
                    ldsm_x4(w2lk + np * 2304 + kk * 32, bl);
                    mma16816(ac2[0][2*np],   A2h[0][kk], bh);
                    mma16816(ac2[0][2*np+1], A2h[0][kk], bh + 2);
                    mma16816(ac2[1][2*np],   A2h[1][kk], bh);
                    mma16816(ac2[1][2*np+1], A2h[1][kk], bh + 2);
                    mma16816(ac2[0][2*np],   A2h[0][kk], bl);
                    mma16816(ac2[0][2*np+1], A2h[0][kk], bl + 2);
                    mma16816(ac2[1][2*np],   A2h[1][kk], bl);
                    mma16816(ac2[1][2*np+1], A2h[1][kk], bl + 2);
                    mma16816(ac2[0][2*np],   A2l[0][kk], bh);
                    mma16816(ac2[0][2*np+1], A2l[0][kk], bh + 2);
                    mma16816(ac2[1][2*np],   A2l[1][kk], bh);
                    mma16816(ac2[1][2*np+1], A2l[1][kk], bh + 2);
                }
            }

            float sl[8], ql[8];
            #pragma unroll
            for (int j = 0; j < 8; ++j) { sl[j] = 0.f; ql[j] = 0.f; }
            #pragma unroll
            for (int mt = 0; mt < 2; ++mt) {
                const int r0 = geBase + R0 + mt * 16 + g;
                #pragma unroll
                for (int nt = 0; nt < 4; ++nt) {
                    const int col = nt * 8 + 2 * cq;
                    float v00 = elu_f(ac2[mt][nt][0]);
                    float v01 = elu_f(ac2[mt][nt][1]);
                    float v10 = elu_f(ac2[mt][nt][2]);
                    float v11 = elu_f(ac2[mt][nt][3]);
                    g_O[(size_t)(k * 32 + col) * BE_ + r0]         = v00;
                    g_O[(size_t)(k * 32 + col + 1) * BE_ + r0]     = v01;
                    g_O[(size_t)(k * 32 + col) * BE_ + r0 + 8]     = v10;
                    g_O[(size_t)(k * 32 + col + 1) * BE_ + r0 + 8] = v11;
                    sl[nt * 2]     += v00 + v10;
                    ql[nt * 2]     += v00 * v00 + v10 * v10;
                    sl[nt * 2 + 1] += v01 + v11;
                    ql[nt * 2 + 1] += v01 * v01 + v11 * v11;
                }
            }
            #pragma unroll
            for (int j = 0; j < 8; ++j) {
                #pragma unroll
                for (int off = 4; off < 32; off <<= 1) {
                    sl[j] += __shfl_xor_sync(0xffffffffu, sl[j], off);
                    ql[j] += __shfl_xor_sync(0xffffffffu, ql[j], off);
                }
            }
            if (lid < 4) {
                #pragma unroll
                for (int nt = 0; nt < 4; ++nt) {
                    atomicAdd(&SSUM[k * 32 + nt * 8 + 2 * lid],     sl[nt * 2]);
                    atomicAdd(&SSQ [k * 32 + nt * 8 + 2 * lid],     ql[nt * 2]);
                    atomicAdd(&SSUM[k * 32 + nt * 8 + 2 * lid + 1], sl[nt * 2 + 1]);
                    atomicAdd(&SSQ [k * 32 + nt * 8 + 2 * lid + 1], ql[nt * 2 + 1]);
                }
            }
        }
        __syncthreads();
        if (tid < 64) { atomicAdd(&g_esum[tid], SSUM[tid]); atomicAdd(&g_esq[tid], SSQ[tid]); }
    } else {
        // ================= NODE PATH =================
        const int nb = (blockIdx.x - 4032) * 128;
        {
            const uint32_t* gv1h = (const uint32_t*)g_wv1h;
            const uint32_t* gv1l = (const uint32_t*)g_wv1l;
            const uint32_t* gv2h = (const uint32_t*)g_wv2h;
            const uint32_t* gv2l = (const uint32_t*)g_wv2l;
            for (int idx = tid; idx < 1024; idx += 128) {   // node W1: [64n][16w]
                int w = idx & 15, n = idx >> 4;
                W1hw[n * 36 + w] = gv1h[idx];
                W1lw[n * 36 + w] = gv1l[idx];
            }
            for (int idx = tid; idx < 2048; idx += 128) {   // node W2: [32n][32w]
                int w = idx & 31, n = idx >> 5;
                W2hw[n * 36 + w] = gv2h[idx];
                W2lw[n * 36 + w] = gv2l[idx];
            }
            if (tid < 64) { SB1[tid] = vb1[tid]; SSUM[tid] = 0.f; SSQ[tid] = 0.f; }
            if (tid < 32) SB2[tid] = vb2[tid];
        }

        // gather A fragments once from g_agg
        uint32_t Ah[2][2][4], Al[2][2][4];
        #pragma unroll
        for (int mt = 0; mt < 2; ++mt) {
            #pragma unroll
            for (int kk = 0; kk < 2; ++kk) {
                const int c0 = kk * 16 + 2 * cq;
                const float* b0 = g_agg + (size_t)(nb + R0 + mt * 16 + g) * 32;
                const float* b1 = b0 + 8 * 32;
                float2 f0 = *(const float2*)(b0 + c0);
                float2 f1 = *(const float2*)(b1 + c0);
                float2 f2 = *(const float2*)(b0 + c0 + 8);
                float2 f3 = *(const float2*)(b1 + c0 + 8);
                split2(f0.x, f0.y, Ah[mt][kk][0], Al[mt][kk][0]);
                split2(f1.x, f1.y, Ah[mt][kk][1], Al[mt][kk][1]);
                split2(f2.x, f2.y, Ah[mt][kk][2], Al[mt][kk][2]);
                split2(f3.x, f3.y, Ah[mt][kk][3], Al[mt][kk][3]);
            }
        }
        __syncthreads();

        const uint32_t w1hk = smb + W1H_B + b4off;
        const uint32_t w1lk = smb + W1L_B + b4off;
        const uint32_t w2hk = smb + W2H_B + b4off;
        const uint32_t w2lk = smb + W2L_B + b4off;

        float acc[2][8][4];
        #pragma unroll
        for (int nt = 0; nt < 8; ++nt) {
            float bb0 = SB1[nt * 8 + 2 * cq];
            float bb1 = SB1[nt * 8 + 2 * cq + 1];
            acc[0][nt][0] = bb0; acc[0][nt][1] = bb1;
            acc[0][nt][2] = bb0; acc[0][nt][3] = bb1;
            acc[1][nt][0] = bb0; acc[1][nt][1] = bb1;
            acc[1][nt][2] = bb0; acc[1][nt][3] = bb1;
        }
        #pragma unroll
        for (int kk = 0; kk < 2; ++kk) {
            #pragma unroll
            for (int np = 0; np < 4; ++np) {
                uint32_t bh[4], bl[4];
                ldsm_x4(w1hk + np * 2304 + kk * 32, bh);
                ldsm_x4(w1lk + np * 2304 + kk * 32, bl);
                mma16816(acc[0][2*np],   Ah[0][kk], bh);
                mma16816(acc[0][2*np+1], Ah[0][kk], bh + 2);
                mma16816(acc[1][2*np],   Ah[1][kk], bh);
                mma16816(acc[1][2*np+1], Ah[1][kk], bh + 2);
                mma16816(acc[0][2*np],   Ah[0][kk], bl);
                mma16816(acc[0][2*np+1], Ah[0][kk], bl + 2);
                mma16816(acc[1][2*np],   Ah[1][kk], bl);
                mma16816(acc[1][2*np+1], Ah[1][kk], bl + 2);
                mma16816(acc[0][2*np],   Al[0][kk], bh);
                mma16816(acc[0][2*np+1], Al[0][kk], bh + 2);
                mma16816(acc[1][2*np],   Al[1][kk], bh);
                mma16816(acc[1][2*np+1], Al[1][kk], bh + 2);
            }
        }

        uint32_t A2h[2][4][4], A2l[2][4][4];
        #pragma unroll
        for (int mt = 0; mt < 2; ++mt) {
            #pragma unroll
            for (int kk = 0; kk < 4; ++kk) {
                float v00 = elu_f(acc[mt][2 * kk][0]);
                float v01 = elu_f(acc[mt][2 * kk][1]);
                float v10 = elu_f(acc[mt][2 * kk][2]);
                float v11 = elu_f(acc[mt][2 * kk][3]);
                float w00 = elu_f(acc[mt][2 * kk + 1][0]);
                float w01 = elu_f(acc[mt][2 * kk + 1][1]);
                float w10 = elu_f(acc[mt][2 * kk + 1][2]);
                float w11 = elu_f(acc[mt][2 * kk + 1][3]);
                split2(v00, v01, A2h[mt][kk][0], A2l[mt][kk][0]);
                split2(v10, v11, A2h[mt][kk][1], A2l[mt][kk][1]);
                split2(w00, w01, A2h[mt][kk][2], A2l[mt][kk][2]);
                split2(w10, w11, A2h[mt][kk][3], A2l[mt][kk][3]);
            }
        }

        float ac2[2][4][4];
        #pragma unroll
        for (int nt = 0; nt < 4; ++nt) {
            float bb0 = SB2[nt * 8 + 2 * cq];
            float bb1 = SB2[nt * 8 + 2 * cq + 1];
            ac2[0][nt][0] = bb0; ac2[0][nt][1] = bb1;
            ac2[0][nt][2] = bb0; ac2[0][nt][3] = bb1;
            ac2[1][nt][0] = bb0; ac2[1][nt][1] = bb1;
            ac2[1][nt][2] = bb0; ac2[1][nt][3] = bb1;
        }
        #pragma unroll
        for (int kk = 0; kk < 4; ++kk) {
            #pragma unroll
            for (int np = 0; np < 2; ++np) {
                uint32_t bh[4], bl[4];
                ldsm_x4(w2hk + np * 2304 + kk * 32, bh);
                ldsm_x4(w2lk + np * 2304 + kk * 32, bl);
                mma16816(ac2[0][2*np],   A2h[0][kk], bh);
                mma16816(ac2[0][2*np+1], A2h[0][kk], bh + 2);
                mma16816(ac2[1][2*np],   A2h[1][kk], bh);
                mma16816(ac2[1][2*np+1], A2h[1][kk], bh + 2);
                mma16816(ac2[0][2*np],   A2h[0][kk], bl);
                mma16816(ac2[0][2*np+1], A2h[0][kk], bl + 2);
                mma16816(ac2[1][2*np],   A2h[1][kk], bl);
                mma16816(ac2[1][2*np+1], A2h[1][kk], bl + 2);
                mma16816(ac2[0][2*np],   A2l[0][kk], bh);
                mma16816(ac2[0][2*np+1], A2l[0][kk], bh + 2);
                mma16816(ac2[1][2*np],   A2l[1][kk], bh);
                mma16816(ac2[1][2*np+1], A2l[1][kk], bh + 2);
            }
        }

        float sl[8], ql[8];
        #pragma unroll
        for (int j = 0; j < 8; ++j) { sl[j] = 0.f; ql[j] = 0.f; }
        #pragma unroll
        for (int mt = 0; mt < 2; ++mt) {
            const int n0 = nb + R0 + mt * 16 + g;
            #pragma unroll
            for (int nt = 0; nt < 4; ++nt) {
                const int col = nt * 8 + 2 * cq;
                float v00 = elu_f(ac2[mt][nt][0]);
                float v01 = elu_f(ac2[mt][nt][1]);
                float v10 = elu_f(ac2[mt][nt][2]);
                float v11 = elu_f(ac2[mt][nt][3]);
                *(float2*)(g_ov + (size_t)n0 * 32 + col)       = make_float2(v00, v01);
                *(float2*)(g_ov + (size_t)(n0 + 8) * 32 + col) = make_float2(v10, v11);
                sl[nt * 2]     += v00 + v10;
                ql[nt * 2]     += v00 * v00 + v10 * v10;
                sl[nt * 2 + 1] += v01 + v11;
                ql[nt * 2 + 1] += v01 * v01 + v11 * v11;
            }
        }
        #pragma unroll
        for (int j = 0; j < 8; ++j) {
            #pragma unroll
            for (int off = 4; off < 32; off <<= 1) {
                sl[j] += __shfl_xor_sync(0xffffffffu, sl[j], off);
                ql[j] += __shfl_xor_sync(0xffffffffu, ql[j], off);
            }
        }
        if (lid < 4) {
            #pragma unroll
            for (int nt = 0; nt < 4; ++nt) {
                atomicAdd(&SSUM[nt * 8 + 2 * lid],     sl[nt * 2]);
                atomicAdd(&SSQ [nt * 8 + 2 * lid],     ql[nt * 2]);
                atomicAdd(&SSUM[nt * 8 + 2 * lid + 1], sl[nt * 2 + 1]);
                atomicAdd(&SSQ [nt * 8 + 2 * lid + 1], ql[nt * 2 + 1]);
            }
        }
        __syncthreads();
        if (tid < 32) { atomicAdd(&g_nsum[tid], SSUM[tid]); atomicAdd(&g_nsq[tid], SSQ[tid]); }
    }
}

// ---------------------------------------------------------------------------
// C) fused post-pass: node_norm (blocks 0..1023) | edge_out (1024..3039)
// ---------------------------------------------------------------------------
__global__ __launch_bounds__(256) void postpass(
    const float* __restrict__ et,
    const float* __restrict__ eg, const float* __restrict__ ebet,
    const float* __restrict__ vg, const float* __restrict__ vbet,
    float* __restrict__ dv, float* __restrict__ de)
{
    __shared__ float A[64], C[64];
    const int bx = blockIdx.x, tid = threadIdx.x;

    if (bx < 1024) {
        if (tid < 32) {
            const float inv_cnt = 1.f / 8192.f;
            float mu = g_nsum[tid] * inv_cnt;
            float var = g_nsq[tid] * inv_cnt - mu * mu;
            float a = vg[tid] * rsqrtf(var + 1e-5f);
            A[tid] = a; C[tid] = vbet[tid] - mu * a;
        }
        __syncthreads();
        int idx = bx * 256 + tid;
        int c = idx & 31;
        dv[idx] = g_ov[idx] * A[c] + C[c];
        return;
    }

    if (tid < 64) {
        const float inv_cnt = 1.f / (float)BE_;
        float mu = g_esum[tid] * inv_cnt;
        float var = g_esq[tid] * inv_cnt - mu * mu;
        float a = eg[tid] * rsqrtf(var + 1e-5f);
        A[tid] = a; C[tid] = ebet[tid] - mu * a;
    }
    __syncthreads();

    const int ge = (bx - 1024) * 256 + tid;
    const float2 w = reinterpret_cast<const float2*>(et)[ge];
    float4* dst = (float4*)(de + (size_t)ge * 32);
    #pragma unroll
    for (int i = 0; i < 8; ++i) {
        float4 o;
        #pragma unroll
        for (int j = 0; j < 4; ++j) {
            const int c = 4 * i + j;
            float x0 = g_O[(size_t)c * BE_ + ge];
            float x1 = g_O[(size_t)(32 + c) * BE_ + ge];
            float r = (A[c] * x0 + C[c]) * w.x + (A[32 + c] * x1 + C[32 + c]) * w.y;
            (&o.x)[j] = r;
        }
        dst[i] = o;
    }
}

// ---------------------------------------------------------------------------
extern "C" void kernel_launch(void* const* d_in, const int* in_sizes, int n_in,
                              void* d_out, int out_size)
{
    const float* v0   = (const float*)d_in[0];
    const float* e0   = (const float*)d_in[1];
    const float* et   = (const float*)d_in[2];
    const float* vW1  = (const float*)d_in[3];
    const float* vb1  = (const float*)d_in[4];
    const float* vW2  = (const float*)d_in[5];
    const float* vb2  = (const float*)d_in[6];
    const float* vg   = (const float*)d_in[7];
    const float* vbet = (const float*)d_in[8];
    const float* eW1  = (const float*)d_in[9];
    const float* eb1  = (const float*)d_in[10];
    const float* eW2  = (const float*)d_in[11];
    const float* eb2  = (const float*)d_in[12];
    const float* eg   = (const float*)d_in[13];
    const float* ebet = (const float*)d_in[14];
    float* out = (float*)d_out;

    cudaFuncSetAttribute(mlp_hmma, cudaFuncAttributeMaxDynamicSharedMemorySize, EH_SMEM);
    cudaFuncSetAttribute(mlp_hmma, cudaFuncAttributePreferredSharedMemoryCarveout, 100);

    prepass<<<5088, 256>>>(e0, eW1, eW2, vW1, vW2, out + ZERO_OFF);
    mlp_hmma<<<4096, 128, EH_SMEM>>>(v0, eb1, eb2, vb1, vb2);
    postpass<<<3040, 256>>>(et, eg, ebet, vg, vbet, out, out + DE_OFF);

    (void)in_sizes; (void)n_in; (void)out_size;
}

// round 12
// speedup vs baseline: 1.2339x; 1.1190x over previous
#include <cuda_runtime.h>
#include <cuda_bf16.h>
#include <cuda_fp16.h>
#include <cstdint>

// ---------------------------------------------------------------------------
// NRI decoder step. Edge+node MLPs on HMMA (mma.sync bf16 2-way split)
// g_O stored as half2 channel-pairs; 2 tiles per block.
// Shapes: B=128, N=64, K=2, VDIM=EDIM=32, HID=64, E=4032, BE=516096
// Output: [dv (262144) | de (16515072) | zeros (1032192)] floats
// ---------------------------------------------------------------------------

#define BN_  128
#define NN_  64
#define EE_  4032
#define BE_  516096
#define DV_ELEMS   262144
#define ZERO_ELEMS 1032192
#define DE_OFF     262144
#define ZERO_OFF   16777216

using ull = unsigned long long;

// scratch (device globals; no runtime allocation)
__device__ uint32_t g_O16[(size_t)32 * BE_]; // edge outputs, half2 per word:
                                             // word [(k*16+colpair)][ge]
__device__ float g_agg[BN_ * NN_ * 32];
__device__ float g_ov[BN_ * NN_ * 32];       // node MLP outputs [node][32]
__device__ float g_esum[64], g_esq[64];
__device__ float g_nsum[32], g_nsq[32];
// pre-split, pre-transposed weights (B-operand layout, k contiguous)
__device__ __nv_bfloat16 g_w1h[8192], g_w1l[8192];   // edge W1 [2][64 n][64 f]
__device__ __nv_bfloat16 g_w2h[4096], g_w2l[4096];   // edge W2 [2][32 n][64 h]
__device__ __nv_bfloat16 g_wv1h[2048], g_wv1l[2048]; // node W1 [64 n][32 f]
__device__ __nv_bfloat16 g_wv2h[2048], g_wv2l[2048]; // node W2 [32 n][64 h]

__device__ __forceinline__ float elu_f(float x) {
    return x > 0.f ? x : (__expf(x) - 1.f);
}
__device__ __forceinline__ uint32_t smem_u32(const void* p) {
    uint32_t a;
    asm("{ .reg .u64 t; cvta.to.shared.u64 t, %1; cvt.u32.u64 %0, t; }" : "=r"(a) : "l"(p));
    return a;
}
// fast 2-way bf16 split: h = bf16x2{lo=a,hi=b}; l = bf16x2 of residuals
__device__ __forceinline__ void split2(float a, float b, uint32_t& h, uint32_t& l) {
    uint32_t hh;
    asm("cvt.rn.bf16x2.f32 %0, %1, %2;" : "=r"(hh) : "f"(b), "f"(a));
    float fa = __uint_as_float(hh << 16);
    float fb = __uint_as_float(hh & 0xFFFF0000u);
    float ra = a - fa, rb = b - fb;
    uint32_t ll;
    asm("cvt.rn.bf16x2.f32 %0, %1, %2;" : "=r"(ll) : "f"(rb), "f"(ra));
    h = hh; l = ll;
}
__device__ __forceinline__ uint32_t packh2(float lo, float hi) {
    uint32_t r;
    asm("cvt.rn.f16x2.f32 %0, %1, %2;" : "=r"(r) : "f"(hi), "f"(lo));
    return r;
}

// ---- warp MMA helpers ------------------------------------------------------
__device__ __forceinline__ void ldsm_x4(uint32_t addr, uint32_t r[4]) {
    asm volatile("ldmatrix.sync.aligned.m8n8.x4.shared.b16 {%0,%1,%2,%3}, [%4];"
        : "=r"(r[0]), "=r"(r[1]), "=r"(r[2]), "=r"(r[3]) : "r"(addr));
}
__device__ __forceinline__ void mma16816(float c[4], const uint32_t a[4], const uint32_t b[2]) {
    asm volatile("mma.sync.aligned.m16n8k16.row.col.f32.bf16.bf16.f32 "
        "{%0,%1,%2,%3}, {%4,%5,%6,%7}, {%8,%9}, {%0,%1,%2,%3};"
        : "+f"(c[0]), "+f"(c[1]), "+f"(c[2]), "+f"(c[3])
        : "r"(a[0]), "r"(a[1]), "r"(a[2]), "r"(a[3]), "r"(b[0]), "r"(b[1]));
}

// ---------------------------------------------------------------------------
// A) fused pre-pass: zeros+stats | weight prep (edge+node) | aggregation
// ---------------------------------------------------------------------------
__global__ __launch_bounds__(256) void prepass(
    const float* __restrict__ e0,
    const float* __restrict__ w1, const float* __restrict__ w2,
    const float* __restrict__ vw1, const float* __restrict__ vw2,
    float* __restrict__ zout)
{
    const int bx = blockIdx.x, tid = threadIdx.x;
    if (bx < 4032) {
        int idx = bx * 256 + tid;
        zout[idx] = 0.f;
        if (bx == 0) {
            if (tid < 64) { g_esum[tid] = 0.f; g_esq[tid] = 0.f; }
            else if (tid < 96) { g_nsum[tid - 64] = 0.f; g_nsq[tid - 64] = 0.f; }
        }
        return;
    }
    if (bx < 4064) {
        int t = (bx - 4032) * 256 + tid;        // 8192 threads
        {   // edge w1: t = (k*64+n)*64+f  <-  w1[(k*64+f)*64+n]
            int f = t & 63, n = (t >> 6) & 63, k = t >> 12;
            float v = w1[(k * 64 + f) * 64 + n];
            __nv_bfloat16 h = __float2bfloat16(v);
            g_w1h[t] = h;
            g_w1l[t] = __float2bfloat16(v - __bfloat162float(h));
        }
        if (t < 4096) {  // edge w2
            int hh = t & 63, n = (t >> 6) & 31, k = t >> 11;
            float v = w2[(k * 64 + hh) * 32 + n];
            __nv_bfloat16 h = __float2bfloat16(v);
            g_w2h[t] = h;
            g_w2l[t] = __float2bfloat16(v - __bfloat162float(h));
        }
        if (t < 2048) {  // node w1: t = n*32+f  <-  vw1[f*64+n]
            int f = t & 31, n = t >> 5;
            float v = vw1[f * 64 + n];
            __nv_bfloat16 h = __float2bfloat16(v);
            g_wv1h[t] = h;
            g_wv1l[t] = __float2bfloat16(v - __bfloat162float(h));
        }
        if (t < 2048) {  // node w2: t = n*64+h  <-  vw2[h*32+n]
            int hh = t & 63, n = t >> 6;
            float v = vw2[hh * 32 + n];
            __nv_bfloat16 h = __float2bfloat16(v);
            g_wv2h[t] = h;
            g_wv2l[t] = __float2bfloat16(v - __bfloat162float(h));
        }
        return;
    }
    {   // edge2node aggregation
        int gw = ((bx - 4064) * 256 + tid) >> 5;
        int lane = tid & 31;
        int b = gw >> 6, j = gw & 63;
        const float* base = e0 + (size_t)b * (NN_ * 63 * 32) + lane;
        float acc = 0.f;
        #pragma unroll 4
        for (int i = 0; i < 64; ++i) {
            if (i == j) continue;
            int jj = (j < i) ? j : j - 1;
            acc += base[(i * 63 + jj) * 32];
        }
        g_agg[gw * 32 + lane] = acc * (1.f / 64.f);
    }
}

// ---------------------------------------------------------------------------
// B) unified HMMA kernel, 2 tiles per block.
//    blocks 0..2015 edge (tiles 2bx, 2bx+1), 2016..2047 node (2 tiles each)
// smem (bytes):
//   0      W1h [2k][64 n][72 b16]   18432
//   18432  W1l                       18432
//   36864  W2h [2k][32 n][72]        9216
//   46080  W2l                       9216
//   55296  CTRL: SB1[128] SB2[64] SSUM[64] SSQ[64]  1280
// ---------------------------------------------------------------------------
#define W1H_B  0
#define W1L_B  18432
#define W2H_B  36864
#define W2L_B  46080
#define CTRL_B 55296
#define EH_SMEM 56576

__global__ __launch_bounds__(128, 3) void mlp_hmma(
    const float* __restrict__ v0,
    const float* __restrict__ eb1, const float* __restrict__ eb2,
    const float* __restrict__ vb1, const float* __restrict__ vb2)
{
    extern __shared__ char sm[];
    const uint32_t smb = smem_u32(sm);
    const int tid = threadIdx.x, wid = tid >> 5, lid = tid & 31;
    const int R0 = wid * 32;

    float* SB1  = (float*)(sm + CTRL_B);
    float* SB2  = (float*)(sm + CTRL_B + 512);
    float* SSUM = (float*)(sm + CTRL_B + 768);
    float* SSQ  = (float*)(sm + CTRL_B + 1024);

    const int b4off = (lid & 7) * 144 + ((lid >> 3) & 1) * 16 + ((lid >> 4) & 1) * 1152;
    const int g  = lid >> 2;
    const int cq = lid & 3;

    uint32_t* W1hw = (uint32_t*)(sm + W1H_B);
    uint32_t* W1lw = (uint32_t*)(sm + W1L_B);
    uint32_t* W2hw = (uint32_t*)(sm + W2H_B);
    uint32_t* W2lw = (uint32_t*)(sm + W2L_B);

    if (blockIdx.x < 2016) {
        // ================= EDGE PATH (2 tiles) =================
        {
            const uint32_t* gw1h = (const uint32_t*)g_w1h;
            const uint32_t* gw1l = (const uint32_t*)g_w1l;
            const uint32_t* gw2h = (const uint32_t*)g_w2h;
            const uint32_t* gw2l = (const uint32_t*)g_w2l;
            for (int idx = tid; idx < 4096; idx += 128) {
                int w = idx & 31, n = (idx >> 5) & 63, kz = idx >> 11;
                W1hw[kz * 2304 + n * 36 + w] = gw1h[idx];
                W1lw[kz * 2304 + n * 36 + w] = gw1l[idx];
            }
            for (int idx = tid; idx < 2048; idx += 128) {
                int w = idx & 31, n = (idx >> 5) & 31, kz = idx >> 10;
                W2hw[kz * 1152 + n * 36 + w] = gw2h[idx];
                W2lw[kz * 1152 + n * 36 + w] = gw2l[idx];
            }
            if (tid < 128) SB1[tid] = eb1[tid];
            if (tid < 64)  { SB2[tid] = eb2[tid]; SSUM[tid] = 0.f; SSQ[tid] = 0.f; }
        }
        __syncthreads();

        const uint32_t bW1h4 = smb + W1H_B + b4off;
        const uint32_t bW1l4 = smb + W1L_B + b4off;
        const uint32_t bW2h4 = smb + W2H_B + b4off;
        const uint32_t bW2l4 = smb + W2L_B + b4off;

        #pragma unroll 1
        for (int t = 0; t < 2; ++t) {
            const int tileIdx = blockIdx.x * 2 + t;
            const int geT = tileIdx * 128 + R0;
            int offR[4], offS[4];
            #pragma unroll
            for (int m2 = 0; m2 < 4; ++m2) {
                int mt = m2 >> 1, rs = (m2 & 1) * 8;
                int gid = geT + mt * 16 + g + rs;
                int b = gid / EE_;
                int e = gid - b * EE_;
                int i0 = e / 63, jj = e - i0 * 63;
                int rc = (jj < i0) ? jj : jj + 1;
                offR[m2] = (b * 64 + rc) * 32;
                offS[m2] = (b * 64 + i0) * 32;
            }

            uint32_t Ah[2][4][4], Al[2][4][4];
            #pragma unroll
            for (int mt = 0; mt < 2; ++mt) {
                #pragma unroll
                for (int kk = 0; kk < 4; ++kk) {
                    const int c0 = (kk & 1) * 16 + 2 * cq;
                    const float* b0 = v0 + ((kk < 2) ? offR[mt * 2]     : offS[mt * 2]);
                    const float* b1 = v0 + ((kk < 2) ? offR[mt * 2 + 1] : offS[mt * 2 + 1]);
                    float2 f0 = *(const float2*)(b0 + c0);
                    float2 f1 = *(const float2*)(b1 + c0);
                    float2 f2 = *(const float2*)(b0 + c0 + 8);
                    float2 f3 = *(const float2*)(b1 + c0 + 8);
                    split2(f0.x, f0.y, Ah[mt][kk][0], Al[mt][kk][0]);
                    split2(f1.x, f1.y, Ah[mt][kk][1], Al[mt][kk][1]);
                    split2(f2.x, f2.y, Ah[mt][kk][2], Al[mt][kk][2]);
                    split2(f3.x, f3.y, Ah[mt][kk][3], Al[mt][kk][3]);
                }
            }

            const int geBase = tileIdx * 128;

            #pragma unroll 1
            for (int k = 0; k < 2; ++k) {
                const float* SB1k = SB1 + k * 64;
                const float* SB2k = SB2 + k * 32;
                const uint32_t w1hk = bW1h4 + k * 9216;
                const uint32_t w1lk = bW1l4 + k * 9216;
                const uint32_t w2hk = bW2h4 + k * 4608;
                const uint32_t w2lk = bW2l4 + k * 4608;

                float acc[2][8][4];
                #pragma unroll
                for (int nt = 0; nt < 8; ++nt) {
                    float bb0 = SB1k[nt * 8 + 2 * cq];
                    float bb1 = SB1k[nt * 8 + 2 * cq + 1];
                    acc[0][nt][0] = bb0; acc[0][nt][1] = bb1;
                    acc[0][nt][2] = bb0; acc[0][nt][3] = bb1;
                    acc[1][nt][0] = bb0; acc[1][nt][1] = bb1;
                    acc[1][nt][2] = bb0; acc[1][nt][3] = bb1;
                }
                #pragma unroll
                for (int kk = 0; kk < 4; ++kk) {
                    #pragma unroll
                    for (int np = 0; np < 4; ++np) {
                        uint32_t bh[4], bl[4];
                        ldsm_x4(w1hk + np * 2304 + kk * 32, bh);
                        ldsm_x4(w1lk + np * 2304 + kk * 32, bl);
                        mma16816(acc[0][2*np],   Ah[0][kk], bh);
                        mma16816(acc[0][2*np+1], Ah[0][kk], bh + 2);
                        mma16816(acc[1][2*np],   Ah[1][kk], bh);
                        mma16816(acc[1][2*np+1], Ah[1][kk], bh + 2);
                        mma16816(acc[0][2*np],   Ah[0][kk], bl);
                        mma16816(acc[0][2*np+1], Ah[0][kk], bl + 2);
                        mma16816(acc[1][2*np],   Ah[1][kk], bl);
                        mma16816(acc[1][2*np+1], Ah[1][kk], bl + 2);
                        mma16816(acc[0][2*np],   Al[0][kk], bh);
                        mma16816(acc[0][2*np+1], Al[0][kk], bh + 2);
                        mma16816(acc[1][2*np],   Al[1][kk], bh);
                        mma16816(acc[1][2*np+1], Al[1][kk], bh + 2);
                    }
                }

                uint32_t A2h[2][4][4], A2l[2][4][4];
                #pragma unroll
                for (int mt = 0; mt < 2; ++mt) {
                    #pragma unroll
                    for (int kk = 0; kk < 4; ++kk) {
                        float v00 = elu_f(acc[mt][2 * kk][0]);
                        float v01 = elu_f(acc[mt][2 * kk][1]);
                        float v10 = elu_f(acc[mt][2 * kk][2]);
                        float v11 = elu_f(acc[mt][2 * kk][3]);
                        float w00 = elu_f(acc[mt][2 * kk + 1][0]);
                        float w01 = elu_f(acc[mt][2 * kk + 1][1]);
                        float w10 = elu_f(acc[mt][2 * kk + 1][2]);
                        float w11 = elu_f(acc[mt][2 * kk + 1][3]);
                        split2(v00, v01, A2h[mt][kk][0], A2l[mt][kk][0]);
                        split2(v10, v11, A2h[mt][kk][1], A2l[mt][kk][1]);
                        split2(w00, w01, A2h[mt][kk][2], A2l[mt][kk][2]);
                        split2(w10, w11, A2h[mt][kk][3], A2l[mt][kk][3]);
                    }
                }

                float ac2[2][4][4];
                #pragma unroll
                for (int nt = 0; nt < 4; ++nt) {
                    float bb0 = SB2k[nt * 8 + 2 * cq];
                    float bb1 = SB2k[nt * 8 + 2 * cq + 1];
                    ac2[0][nt][0] = bb0; ac2[0][nt][1] = bb1;
                    ac2[0][nt][2] = bb0; ac2[0][nt][3] = bb1;
                    ac2[1][nt][0] = bb0; ac2[1][nt][1] = bb1;
                    ac2[1][nt][2] = bb0; ac2[1][nt][3] = bb1;
                }
                #pragma unroll
                for (int kk = 0; kk < 4; ++kk) {
                    #pragma unroll
                    for (int np = 0; np < 2; ++np) {
                        uint32_t bh[4], bl[4];
                        ldsm_x4(w2hk + np * 2304 + kk * 32, bh);
                        ldsm_x4(w2lk + np * 2304 + kk * 32, bl);
                        mma16816(ac2[0][2*np],   A2h[0][kk], bh);
                        mma16816(ac2[0][2*np+1], A2h[0][kk], bh + 2);
                        mma16816(ac2[1][2*np],   A2h[1][kk], bh);
                        mma16816(ac2[1][2*np+1], A2h[1][kk], bh + 2);
                        mma16816(ac2[0][2*np],   A2h[0][kk], bl);
                        mma16816(ac2[0][2*np+1], A2h[0][kk], bl + 2);
                        mma16816(ac2[1][2*np],   A2h[1][kk], bl);
                        mma16816(ac2[1][2*np+1], A2h[1][kk], bl + 2);
                        mma16816(ac2[0][2*np],   A2l[0][kk], bh);
                        mma16816(ac2[0][2*np+1], A2l[0][kk], bh + 2);
                        mma16816(ac2[1][2*np],   A2l[1][kk], bh);
                        mma16816(ac2[1][2*np+1], A2l[1][kk], bh + 2);
                    }
                }

                float sl[8], ql[8];
                #pragma unroll
                for (int j = 0; j < 8; ++j) { sl[j] = 0.f; ql[j] = 0.f; }
                #pragma unroll
                for (int mt = 0; mt < 2; ++mt) {
                    const int r0 = geBase + R0 + mt * 16 + g;
                    #pragma unroll
                    for (int nt = 0; nt < 4; ++nt) {
                        const int c2 = nt * 4 + cq;          // channel pair
                        float v00 = elu_f(ac2[mt][nt][0]);
                        float v01 = elu_f(ac2[mt][nt][1]);
                        float v10 = elu_f(ac2[mt][nt][2]);
                        float v11 = elu_f(ac2[mt][nt][3]);
                        g_O16[(size_t)(k * 16 + c2) * BE_ + r0]     = packh2(v00, v01);
                        g_O16[(size_t)(k * 16 + c2) * BE_ + r0 + 8] = packh2(v10, v11);
                        sl[nt * 2]     += v00 + v10;
                        ql[nt * 2]     += v00 * v00 + v10 * v10;
                        sl[nt * 2 + 1] += v01 + v11;
                        ql[nt * 2 + 1] += v01 * v01 + v11 * v11;
                    }
                }
                #pragma unroll
                for (int j = 0; j < 8; ++j) {
                    #pragma unroll
                    for (int off = 4; off < 32; off <<= 1) {
                        sl[j] += __shfl_xor_sync(0xffffffffu, sl[j], off);
                        ql[j] += __shfl_xor_sync(0xffffffffu, ql[j], off);
                    }
                }
                if (lid < 4) {
                    #pragma unroll
                    for (int nt = 0; nt < 4; ++nt) {
                        atomicAdd(&SSUM[k * 32 + nt * 8 + 2 * lid],     sl[nt * 2]);
                        atomicAdd(&SSQ [k * 32 + nt * 8 + 2 * lid],     ql[nt * 2]);
                        atomicAdd(&SSUM[k * 32 + nt * 8 + 2 * lid + 1], sl[nt * 2 + 1]);
                        atomicAdd(&SSQ [k * 32 + nt * 8 + 2 * lid + 1], ql[nt * 2 + 1]);
                    }
                }
            }
        }
        __syncthreads();
        if (tid < 64) { atomicAdd(&g_esum[tid], SSUM[tid]); atomicAdd(&g_esq[tid], SSQ[tid]); }
    } else {
        // ================= NODE PATH (2 tiles) =================
        {
            const uint32_t* gv1h = (const uint32_t*)g_wv1h;
            const uint32_t* gv1l = (const uint32_t*)g_wv1l;
            const uint32_t* gv2h = (const uint32_t*)g_wv2h;
            const uint32_t* gv2l = (const uint32_t*)g_wv2l;
            for (int idx = tid; idx < 1024; idx += 128) {   // node W1: [64n][16w]
                int w = idx & 15, n = idx >> 4;
                W1hw[n * 36 + w] = gv1h[idx];
                W1lw[n * 36 + w] = gv1l[idx];
            }
            for (int idx = tid; idx < 2048; idx += 128) {   // node W2: [32n][32w]
                int w = idx & 31, n = idx >> 5;
                W2hw[n * 36 + w] = gv2h[idx];
                W2lw[n * 36 + w] = gv2l[idx];
            }
            if (tid < 64) { SB1[tid] = vb1[tid]; SSUM[tid] = 0.f; SSQ[tid] = 0.f; }
            if (tid < 32) SB2[tid] = vb2[tid];
        }
        __syncthreads();

        const uint32_t w1hk = smb + W1H_B + b4off;
        const uint32_t w1lk = smb + W1L_B + b4off;
        const uint32_t w2hk = smb + W2H_B + b4off;
        const uint32_t w2lk = smb + W2L_B + b4off;

        #pragma unroll 1
        for (int t = 0; t < 2; ++t) {
            const int nb = ((blockIdx.x - 2016) * 2 + t) * 128;

            uint32_t Ah[2][2][4], Al[2][2][4];
            #pragma unroll
            for (int mt = 0; mt < 2; ++mt) {
                #pragma unroll
                for (int kk = 0; kk < 2; ++kk) {
                    const int c0 = kk * 16 + 2 * cq;
                    const float* b0 = g_agg + (size_t)(nb + R0 + mt * 16 + g) * 32;
                    const float* b1 = b0 + 8 * 32;
                    float2 f0 = *(const float2*)(b0 + c0);
                    float2 f1 = *(const float2*)(b1 + c0);
                    float2 f2 = *(const float2*)(b0 + c0 + 8);
                    float2 f3 = *(const float2*)(b1 + c0 + 8);
                    split2(f0.x, f0.y, Ah[mt][kk][0], Al[mt][kk][0]);
                    split2(f1.x, f1.y, Ah[mt][kk][1], Al[mt][kk][1]);
                    split2(f2.x, f2.y, Ah[mt][kk][2], Al[mt][kk][2]);
                    split2(f3.x, f3.y, Ah[mt][kk][3], Al[mt][kk][3]);
                }
            }

            float acc[2][8][4];
            #pragma unroll
            for (int nt = 0; nt < 8; ++nt) {
                float bb0 = SB1[nt * 8 + 2 * cq];
                float bb1 = SB1[nt * 8 + 2 * cq + 1];
                acc[0][nt][0] = bb0; acc[0][nt][1] = bb1;
                acc[0][nt][2] = bb0; acc[0][nt][3] = bb1;
                acc[1][nt][0] = bb0; acc[1][nt][1] = bb1;
                acc[1][nt][2] = bb0; acc[1][nt][3] = bb1;
            }
            #pragma unroll
            for (int kk = 0; kk < 2; ++kk) {
                #pragma unroll
                for (int np = 0; np < 4; ++np) {
                    uint32_t bh[4], bl[4];
                    ldsm_x4(w1hk + np * 2304 + kk * 32, bh);
                    ldsm_x4(w1lk + np * 2304 + kk * 32, bl);
                    mma16816(acc[0][2*np],   Ah[0][kk], bh);
                    mma16816(acc[0][2*np+1], Ah[0][kk], bh + 2);
                    mma16816(acc[1][2*np],   Ah[1][kk], bh);
                    mma16816(acc[1][2*np+1], Ah[1][kk], bh + 2);
                    mma16816(acc[0][2*np],   Ah[0][kk], bl);
                    mma16816(acc[0][2*np+1], Ah[0][kk], bl + 2);
                    mma16816(acc[1][2*np],   Ah[1][kk], bl);
                    mma16816(acc[1][2*np+1], Ah[1][kk], bl + 2);
                    mma16816(acc[0][2*np],   Al[0][kk], bh);
                    mma16816(acc[0][2*np+1], Al[0][kk], bh + 2);
                    mma16816(acc[1][2*np],   Al[1][kk], bh);
                    mma16816(acc[1][2*np+1], Al[1][kk], bh + 2);
                }
            }

            uint32_t A2h[2][4][4], A2l[2][4][4];
            #pragma unroll
            for (int mt = 0; mt < 2; ++mt) {
                #pragma unroll
                for (int kk = 0; kk < 4; ++kk) {
                    float v00 = elu_f(acc[mt][2 * kk][0]);
                    float v01 = elu_f(acc[mt][2 * kk][1]);
                    float v10 = elu_f(acc[mt][2 * kk][2]);
                    float v11 = elu_f(acc[mt][2 * kk][3]);
                    float w00 = elu_f(acc[mt][2 * kk + 1][0]);
                    float w01 = elu_f(acc[mt][2 * kk + 1][1]);
                    float w10 = elu_f(acc[mt][2 * kk + 1][2]);
                    float w11 = elu_f(acc[mt][2 * kk + 1][3]);
                    split2(v00, v01, A2h[mt][kk][0], A2l[mt][kk][0]);
                    split2(v10, v11, A2h[mt][kk][1], A2l[mt][kk][1]);
                    split2(w00, w01, A2h[mt][kk][2], A2l[mt][kk][2]);
                    split2(w10, w11, A2h[mt][kk][3], A2l[mt][kk][3]);
                }
            }

            float ac2[2][4][4];
            #pragma unroll
            for (int nt = 0; nt < 4; ++nt) {
                float bb0 = SB2[nt * 8 + 2 * cq];
                float bb1 = SB2[nt * 8 + 2 * cq + 1];
                ac2[0][nt][0] = bb0; ac2[0][nt][1] = bb1;
                ac2[0][nt][2] = bb0; ac2[0][nt][3] = bb1;
                ac2[1][nt][0] = bb0; ac2[1][nt][1] = bb1;
                ac2[1][nt][2] = bb0; ac2[1][nt][3] = bb1;
            }
            #pragma unroll
            for (int kk = 0; kk < 4; ++kk) {
                #pragma unroll
                for (int np = 0; np < 2; ++np) {
                    uint32_t bh[4], bl[4];
                    ldsm_x4(w2hk + np * 2304 + kk * 32, bh);
                    ldsm_x4(w2lk + np * 2304 + kk * 32, bl);
                    mma16816(ac2[0][2*np],   A2h[0][kk], bh);
                    mma16816(ac2[0][2*np+1], A2h[0][kk], bh + 2);
                    mma16816(ac2[1][2*np],   A2h[1][kk], bh);
                    mma16816(ac2[1][2*np+1], A2h[1][kk], bh + 2);
                    mma16816(ac2[0][2*np],   A2h[0][kk], bl);
                    mma16816(ac2[0][2*np+1], A2h[0][kk], bl + 2);
                    mma16816(ac2[1][2*np],   A2h[1][kk], bl);
                    mma16816(ac2[1][2*np+1], A2h[1][kk], bl + 2);
                    mma16816(ac2[0][2*np],   A2l[0][kk], bh);
                    mma16816(ac2[0][2*np+1], A2l[0][kk], bh + 2);
                    mma16816(ac2[1][2*np],   A2l[1][kk], bh);
                    mma16816(ac2[1][2*np+1], A2l[1][kk], bh + 2);
                }
            }

            float sl[8], ql[8];
            #pragma unroll
            for (int j = 0; j < 8; ++j) { sl[j] = 0.f; ql[j] = 0.f; }
            #pragma unroll
            for (int mt = 0; mt < 2; ++mt) {
                const int n0 = nb + R0 + mt * 16 + g;
                #pragma unroll
                for (int nt = 0; nt < 4; ++nt) {
                    const int col = nt * 8 + 2 * cq;
                    float v00 = elu_f(ac2[mt][nt][0]);
                    float v01 = elu_f(ac2[mt][nt][1]);
                    float v10 = elu_f(ac2[mt][nt][2]);
                    float v11 = elu_f(ac2[mt][nt][3]);
                    *(float2*)(g_ov + (size_t)n0 * 32 + col)       = make_float2(v00, v01);
                    *(float2*)(g_ov + (size_t)(n0 + 8) * 32 + col) = make_float2(v10, v11);
                    sl[nt * 2]     += v00 + v10;
                    ql[nt * 2]     += v00 * v00 + v10 * v10;
                    sl[nt * 2 + 1] += v01 + v11;
                    ql[nt * 2 + 1] += v01 * v01 + v11 * v11;
                }
            }
            #pragma unroll
            for (int j = 0; j < 8; ++j) {
                #pragma unroll
                for (int off = 4; off < 32; off <<= 1) {
                    sl[j] += __shfl_xor_sync(0xffffffffu, sl[j], off);
                    ql[j] += __shfl_xor_sync(0xffffffffu, ql[j], off);
                }
            }
            if (lid < 4) {
                #pragma unroll
                for (int nt = 0; nt < 4; ++nt) {
                    atomicAdd(&SSUM[nt * 8 + 2 * lid],     sl[nt * 2]);
                    atomicAdd(&SSQ [nt * 8 + 2 * lid],     ql[nt * 2]);
                    atomicAdd(&SSUM[nt * 8 + 2 * lid + 1], sl[nt * 2 + 1]);
                    atomicAdd(&SSQ [nt * 8 + 2 * lid + 1], ql[nt * 2 + 1]);
                }
            }
        }
        __syncthreads();
        if (tid < 32) { atomicAdd(&g_nsum[tid], SSUM[tid]); atomicAdd(&g_nsq[tid], SSQ[tid]); }
    }
}

// ---------------------------------------------------------------------------
// C) fused post-pass: node_norm (blocks 0..1023) | edge_out (1024..3039)
//    edge part reads half2 channel-pairs.
// ---------------------------------------------------------------------------
__global__ __launch_bounds__(256) void postpass(
    const float* __restrict__ et,
    const float* __restrict__ eg, const float* __restrict__ ebet,
    const float* __restrict__ vg, const float* __restrict__ vbet,
    float* __restrict__ dv, float* __restrict__ de)
{
    __shared__ float A[64], C[64];
    const int bx = blockIdx.x, tid = threadIdx.x;

    if (bx < 1024) {
        if (tid < 32) {
            const float inv_cnt = 1.f / 8192.f;
            float mu = g_nsum[tid] * inv_cnt;
            float var = g_nsq[tid] * inv_cnt - mu * mu;
            float a = vg[tid] * rsqrtf(var + 1e-5f);
            A[tid] = a; C[tid] = vbet[tid] - mu * a;
        }
        __syncthreads();
        int idx = bx * 256 + tid;
        int c = idx & 31;
        dv[idx] = g_ov[idx] * A[c] + C[c];
        return;
    }

    if (tid < 64) {
        const float inv_cnt = 1.f / (float)BE_;
        float mu = g_esum[tid] * inv_cnt;
        float var = g_esq[tid] * inv_cnt - mu * mu;
        float a = eg[tid] * rsqrtf(var + 1e-5f);
        A[tid] = a; C[tid] = ebet[tid] - mu * a;
    }
    __syncthreads();

    const int ge = (bx - 1024) * 256 + tid;
    const float2 w = reinterpret_cast<const float2*>(et)[ge];
    float4* dst = (float4*)(de + (size_t)ge * 32);
    #pragma unroll
    for (int i = 0; i < 8; ++i) {
        // channels 4i..4i+3 = pairs 2i, 2i+1
        uint32_t a0 = g_O16[(size_t)(2 * i) * BE_ + ge];
        uint32_t a1 = g_O16[(size_t)(2 * i + 1) * BE_ + ge];
        uint32_t b0 = g_O16[(size_t)(16 + 2 * i) * BE_ + ge];
        uint32_t b1 = g_O16[(size_t)(16 + 2 * i + 1) * BE_ + ge];
        float2 fa0 = __half22float2(*reinterpret_cast<__half2*>(&a0));
        float2 fa1 = __half22float2(*reinterpret_cast<__half2*>(&a1));
        float2 fb0 = __half22float2(*reinterpret_cast<__half2*>(&b0));
        float2 fb1 = __half22float2(*reinterpret_cast<__half2*>(&b1));
        float4 o;
        {
            const int c = 4 * i;
            o.x = (A[c] * fa0.x + C[c]) * w.x + (A[32 + c] * fb0.x + C[32 + c]) * w.y;
        }
        {
            const int c = 4 * i + 1;
            o.y = (A[c] * fa0.y + C[c]) * w.x + (A[32 + c] * fb0.y + C[32 + c]) * w.y;
        }
        {
            const int c = 4 * i + 2;
            o.z = (A[c] * fa1.x + C[c]) * w.x + (A[32 + c] * fb1.x + C[32 + c]) * w.y;
        }
        {
            const int c = 4 * i + 3;
            o.w = (A[c] * fa1.y + C[c]) * w.x + (A[32 + c] * fb1.y + C[32 + c]) * w.y;
        }
        dst[i] = o;
    }
}

// ---------------------------------------------------------------------------
extern "C" void kernel_launch(void* const* d_in, const int* in_sizes, int n_in,
                              void* d_out, int out_size)
{
    const float* v0   = (const float*)d_in[0];
    const float* e0   = (const float*)d_in[1];
    const float* et   = (const float*)d_in[2];
    const float* vW1  = (const float*)d_in[3];
    const float* vb1  = (const float*)d_in[4];
    const float* vW2  = (const float*)d_in[5];
    const float* vb2  = (const float*)d_in[6];
    const float* vg   = (const float*)d_in[7];
    const float* vbet = (const float*)d_in[8];
    const float* eW1  = (const float*)d_in[9];
    const float* eb1  = (const float*)d_in[10];
    const float* eW2  = (const float*)d_in[11];
    const float* eb2  = (const float*)d_in[12];
    const float* eg   = (const float*)d_in[13];
    const float* ebet = (const float*)d_in[14];
    float* out = (float*)d_out;

    cudaFuncSetAttribute(mlp_hmma, cudaFuncAttributeMaxDynamicSharedMemorySize, EH_SMEM);
    cudaFuncSetAttribute(mlp_hmma, cudaFuncAttributePreferredSharedMemoryCarveout, 100);

    prepass<<<5088, 256>>>(e0, eW1, eW2, vW1, vW2, out + ZERO_OFF);
    mlp_hmma<<<2048, 128, EH_SMEM>>>(v0, eb1, eb2, vb1, vb2);
    postpass<<<3040, 256>>>(et, eg, ebet, vg, vbet, out, out + DE_OFF);

    (void)in_sizes; (void)n_in; (void)out_size;
}

// round 13
// speedup vs baseline: 1.4089x; 1.1419x over previous
#include <cuda_runtime.h>
#include <cuda_bf16.h>
#include <cuda_fp16.h>
#include <cstdint>

// ---------------------------------------------------------------------------
// NRI decoder step. Edge+node MLPs on HMMA.
// fp16 A-operand (single), fp16 hi/lo split weights -> 2 MMAs per GEMM term.
// g_O stored as half2 channel-pairs; 2 tiles per block.
// Shapes: B=128, N=64, K=2, VDIM=EDIM=32, HID=64, E=4032, BE=516096
// Output: [dv (262144) | de (16515072) | zeros (1032192)] floats
// ---------------------------------------------------------------------------

#define BN_  128
#define NN_  64
#define EE_  4032
#define BE_  516096
#define DV_ELEMS   262144
#define ZERO_ELEMS 1032192
#define DE_OFF     262144
#define ZERO_OFF   16777216

// scratch (device globals; no runtime allocation)
__device__ uint32_t g_O16[(size_t)32 * BE_]; // edge outputs half2 [(k*16+cp)][ge]
__device__ float g_agg[BN_ * NN_ * 32];
__device__ float g_ov[BN_ * NN_ * 32];       // node MLP outputs [node][32]
__device__ float g_esum[64], g_esq[64];
__device__ float g_nsum[32], g_nsq[32];
// pre-split, pre-transposed fp16 weights (B-operand layout, k contiguous)
__device__ __half g_w1h[8192], g_w1l[8192];   // edge W1 [2][64 n][64 f]
__device__ __half g_w2h[4096], g_w2l[4096];   // edge W2 [2][32 n][64 h]
__device__ __half g_wv1h[2048], g_wv1l[2048]; // node W1 [64 n][32 f]
__device__ __half g_wv2h[2048], g_wv2l[2048]; // node W2 [32 n][64 h]

__device__ __forceinline__ float elu_f(float x) {
    return x > 0.f ? x : (__expf(x) - 1.f);
}
__device__ __forceinline__ uint32_t smem_u32(const void* p) {
    uint32_t a;
    asm("{ .reg .u64 t; cvta.to.shared.u64 t, %1; cvt.u32.u64 %0, t; }" : "=r"(a) : "l"(p));
    return a;
}
__device__ __forceinline__ uint32_t packh2(float lo, float hi) {
    uint32_t r;
    asm("cvt.rn.f16x2.f32 %0, %1, %2;" : "=r"(r) : "f"(hi), "f"(lo));
    return r;
}

// ---- warp MMA helpers (fp16 inputs, fp32 accum) ---------------------------
__device__ __forceinline__ void ldsm_x4(uint32_t addr, uint32_t r[4]) {
    asm volatile("ldmatrix.sync.aligned.m8n8.x4.shared.b16 {%0,%1,%2,%3}, [%4];"
        : "=r"(r[0]), "=r"(r[1]), "=r"(r[2]), "=r"(r[3]) : "r"(addr));
}
__device__ __forceinline__ void mma16816(float c[4], const uint32_t a[4], const uint32_t b[2]) {
    asm volatile("mma.sync.aligned.m16n8k16.row.col.f32.f16.f16.f32 "
        "{%0,%1,%2,%3}, {%4,%5,%6,%7}, {%8,%9}, {%0,%1,%2,%3};"
        : "+f"(c[0]), "+f"(c[1]), "+f"(c[2]), "+f"(c[3])
        : "r"(a[0]), "r"(a[1]), "r"(a[2]), "r"(a[3]), "r"(b[0]), "r"(b[1]));
}

// ---------------------------------------------------------------------------
// A) fused pre-pass: zeros+stats | weight prep (fp16 hi/lo) | aggregation
// ---------------------------------------------------------------------------
__global__ __launch_bounds__(256) void prepass(
    const float* __restrict__ e0,
    const float* __restrict__ w1, const float* __restrict__ w2,
    const float* __restrict__ vw1, const float* __restrict__ vw2,
    float* __restrict__ zout)
{
    const int bx = blockIdx.x, tid = threadIdx.x;
    if (bx < 4032) {
        int idx = bx * 256 + tid;
        zout[idx] = 0.f;
        if (bx == 0) {
            if (tid < 64) { g_esum[tid] = 0.f; g_esq[tid] = 0.f; }
            else if (tid < 96) { g_nsum[tid - 64] = 0.f; g_nsq[tid - 64] = 0.f; }
        }
        return;
    }
    if (bx < 4064) {
        int t = (bx - 4032) * 256 + tid;        // 8192 threads
        {   // edge w1: t = (k*64+n)*64+f  <-  w1[(k*64+f)*64+n]
            int f = t & 63, n = (t >> 6) & 63, k = t >> 12;
            float v = w1[(k * 64 + f) * 64 + n];
            __half h = __float2half(v);
            g_w1h[t] = h;
            g_w1l[t] = __float2half(v - __half2float(h));
        }
        if (t < 4096) {  // edge w2
            int hh = t & 63, n = (t >> 6) & 31, k = t >> 11;
            float v = w2[(k * 64 + hh) * 32 + n];
            __half h = __float2half(v);
            g_w2h[t] = h;
            g_w2l[t] = __float2half(v - __half2float(h));
        }
        if (t < 2048) {  // node w1: t = n*32+f  <-  vw1[f*64+n]
            int f = t & 31, n = t >> 5;
            float v = vw1[f * 64 + n];
            __half h = __float2half(v);
            g_wv1h[t] = h;
            g_wv1l[t] = __float2half(v - __half2float(h));
        }
        if (t < 2048) {  // node w2: t = n*64+h  <-  vw2[h*32+n]
            int hh = t & 63, n = t >> 6;
            float v = vw2[hh * 32 + n];
            __half h = __float2half(v);
            g_wv2h[t] = h;
            g_wv2l[t] = __float2half(v - __half2float(h));
        }
        return;
    }
    {   // edge2node aggregation
        int gw = ((bx - 4064) * 256 + tid) >> 5;
        int lane = tid & 31;
        int b = gw >> 6, j = gw & 63;
        const float* base = e0 + (size_t)b * (NN_ * 63 * 32) + lane;
        float acc = 0.f;
        #pragma unroll 4
        for (int i = 0; i < 64; ++i) {
            if (i == j) continue;
            int jj = (j < i) ? j : j - 1;
            acc += base[(i * 63 + jj) * 32];
        }
        g_agg[gw * 32 + lane] = acc * (1.f / 64.f);
    }
}

// ---------------------------------------------------------------------------
// B) unified HMMA kernel, 2 tiles per block.
//    blocks 0..2015 edge (tiles 2bx, 2bx+1), 2016..2047 node (2 tiles each)
// smem layout identical to r11 (fp16 weights, hi+lo)
// ---------------------------------------------------------------------------
#define W1H_B  0
#define W1L_B  18432
#define W2H_B  36864
#define W2L_B  46080
#define CTRL_B 55296
#define EH_SMEM 56576

__global__ __launch_bounds__(128, 3) void mlp_hmma(
    const float* __restrict__ v0,
    const float* __restrict__ eb1, const float* __restrict__ eb2,
    const float* __restrict__ vb1, const float* __restrict__ vb2)
{
    extern __shared__ char sm[];
    const uint32_t smb = smem_u32(sm);
    const int tid = threadIdx.x, wid = tid >> 5, lid = tid & 31;
    const int R0 = wid * 32;

    float* SB1  = (float*)(sm + CTRL_B);
    float* SB2  = (float*)(sm + CTRL_B + 512);
    float* SSUM = (float*)(sm + CTRL_B + 768);
    float* SSQ  = (float*)(sm + CTRL_B + 1024);

    const int b4off = (lid & 7) * 144 + ((lid >> 3) & 1) * 16 + ((lid >> 4) & 1) * 1152;
    const int g  = lid >> 2;
    const int cq = lid & 3;

    uint32_t* W1hw = (uint32_t*)(sm + W1H_B);
    uint32_t* W1lw = (uint32_t*)(sm + W1L_B);
    uint32_t* W2hw = (uint32_t*)(sm + W2H_B);
    uint32_t* W2lw = (uint32_t*)(sm + W2L_B);

    if (blockIdx.x < 2016) {
        // ================= EDGE PATH (2 tiles) =================
        {
            const uint32_t* gw1h = (const uint32_t*)g_w1h;
            const uint32_t* gw1l = (const uint32_t*)g_w1l;
            const uint32_t* gw2h = (const uint32_t*)g_w2h;
            const uint32_t* gw2l = (const uint32_t*)g_w2l;
            for (int idx = tid; idx < 4096; idx += 128) {
                int w = idx & 31, n = (idx >> 5) & 63, kz = idx >> 11;
                W1hw[kz * 2304 + n * 36 + w] = gw1h[idx];
                W1lw[kz * 2304 + n * 36 + w] = gw1l[idx];
            }
            for (int idx = tid; idx < 2048; idx += 128) {
                int w = idx & 31, n = (idx >> 5) & 31, kz = idx >> 10;
                W2hw[kz * 1152 + n * 36 + w] = gw2h[idx];
                W2lw[kz * 1152 + n * 36 + w] = gw2l[idx];
            }
            if (tid < 128) SB1[tid] = eb1[tid];
            if (tid < 64)  { SB2[tid] = eb2[tid]; SSUM[tid] = 0.f; SSQ[tid] = 0.f; }
        }
        __syncthreads();

        const uint32_t bW1h4 = smb + W1H_B + b4off;
        const uint32_t bW1l4 = smb + W1L_B + b4off;
        const uint32_t bW2h4 = smb + W2H_B + b4off;
        const uint32_t bW2l4 = smb + W2L_B + b4off;

        #pragma unroll 1
        for (int t = 0; t < 2; ++t) {
            const int tileIdx = blockIdx.x * 2 + t;
            const int geT = tileIdx * 128 + R0;
            int offR[4], offS[4];
            #pragma unroll
            for (int m2 = 0; m2 < 4; ++m2) {
                int mt = m2 >> 1, rs = (m2 & 1) * 8;
                int gid = geT + mt * 16 + g + rs;
                int b = gid / EE_;
                int e = gid - b * EE_;
                int i0 = e / 63, jj = e - i0 * 63;
                int rc = (jj < i0) ? jj : jj + 1;
                offR[m2] = (b * 64 + rc) * 32;
                offS[m2] = (b * 64 + i0) * 32;
            }

            // gather A fragments (single fp16, no residual)
            uint32_t Ah[2][4][4];
            #pragma unroll
            for (int mt = 0; mt < 2; ++mt) {
                #pragma unroll
                for (int kk = 0; kk < 4; ++kk) {
                    const int c0 = (kk & 1) * 16 + 2 * cq;
                    const float* b0 = v0 + ((kk < 2) ? offR[mt * 2]     : offS[mt * 2]);
                    const float* b1 = v0 + ((kk < 2) ? offR[mt * 2 + 1] : offS[mt * 2 + 1]);
                    float2 f0 = *(const float2*)(b0 + c0);
                    float2 f1 = *(const float2*)(b1 + c0);
                    float2 f2 = *(const float2*)(b0 + c0 + 8);
                    float2 f3 = *(const float2*)(b1 + c0 + 8);
                    Ah[mt][kk][0] = packh2(f0.x, f0.y);
                    Ah[mt][kk][1] = packh2(f1.x, f1.y);
                    Ah[mt][kk][2] = packh2(f2.x, f2.y);
                    Ah[mt][kk][3] = packh2(f3.x, f3.y);
                }
            }

            const int geBase = tileIdx * 128;

            #pragma unroll 1
            for (int k = 0; k < 2; ++k) {
                const float* SB1k = SB1 + k * 64;
                const float* SB2k = SB2 + k * 32;
                const uint32_t w1hk = bW1h4 + k * 9216;
                const uint32_t w1lk = bW1l4 + k * 9216;
                const uint32_t w2hk = bW2h4 + k * 4608;
                const uint32_t w2lk = bW2l4 + k * 4608;

                float acc[2][8][4];
                #pragma unroll
                for (int nt = 0; nt < 8; ++nt) {
                    float bb0 = SB1k[nt * 8 + 2 * cq];
                    float bb1 = SB1k[nt * 8 + 2 * cq + 1];
                    acc[0][nt][0] = bb0; acc[0][nt][1] = bb1;
                    acc[0][nt][2] = bb0; acc[0][nt][3] = bb1;
                    acc[1][nt][0] = bb0; acc[1][nt][1] = bb1;
                    acc[1][nt][2] = bb0; acc[1][nt][3] = bb1;
                }
                #pragma unroll
                for (int kk = 0; kk < 4; ++kk) {
                    #pragma unroll
                    for (int np = 0; np < 4; ++np) {
                        uint32_t bh[4], bl[4];
                        ldsm_x4(w1hk + np * 2304 + kk * 32, bh);
                        ldsm_x4(w1lk + np * 2304 + kk * 32, bl);
                        mma16816(acc[0][2*np],   Ah[0][kk], bh);
                        mma16816(acc[0][2*np+1], Ah[0][kk], bh + 2);
                        mma16816(acc[1][2*np],   Ah[1][kk], bh);
                        mma16816(acc[1][2*np+1], Ah[1][kk], bh + 2);
                        mma16816(acc[0][2*np],   Ah[0][kk], bl);
                        mma16816(acc[0][2*np+1], Ah[0][kk], bl + 2);
                        mma16816(acc[1][2*np],   Ah[1][kk], bl);
                        mma16816(acc[1][2*np+1], Ah[1][kk], bl + 2);
                    }
                }

                // epilogue 1: ELU, pack fp16 A2 fragments (no residual)
                uint32_t A2h[2][4][4];
                #pragma unroll
                for (int mt = 0; mt < 2; ++mt) {
                    #pragma unroll
                    for (int kk = 0; kk < 4; ++kk) {
                        float v00 = elu_f(acc[mt][2 * kk][0]);
                        float v01 = elu_f(acc[mt][2 * kk][1]);
                        float v10 = elu_f(acc[mt][2 * kk][2]);
                        float v11 = elu_f(acc[mt][2 * kk][3]);
                        float w00 = elu_f(acc[mt][2 * kk + 1][0]);
                        float w01 = elu_f(acc[mt][2 * kk + 1][1]);
                        float w10 = elu_f(acc[mt][2 * kk + 1][2]);
                        float w11 = elu_f(acc[mt][2 * kk + 1][3]);
                        A2h[mt][kk][0] = packh2(v00, v01);
                        A2h[mt][kk][1] = packh2(v10, v11);
                        A2h[mt][kk][2] = packh2(w00, w01);
                        A2h[mt][kk][3] = packh2(w10, w11);
                    }
                }

                float ac2[2][4][4];
                #pragma unroll
                for (int nt = 0; nt < 4; ++nt) {
                    float bb0 = SB2k[nt * 8 + 2 * cq];
                    float bb1 = SB2k[nt * 8 + 2 * cq + 1];
                    ac2[0][nt][0] = bb0; ac2[0][nt][1] = bb1;
                    ac2[0][nt][2] = bb0; ac2[0][nt][3] = bb1;
                    ac2[1][nt][0] = bb0; ac2[1][nt][1] = bb1;
                    ac2[1][nt][2] = bb0; ac2[1][nt][3] = bb1;
                }
                #pragma unroll
                for (int kk = 0; kk < 4; ++kk) {
                    #pragma unroll
                    for (int np = 0; np < 2; ++np) {
                        uint32_t bh[4], bl[4];
                        ldsm_x4(w2hk + np * 2304 + kk * 32, bh);
                        ldsm_x4(w2lk + np * 2304 + kk * 32, bl);
                        mma16816(ac2[0][2*np],   A2h[0][kk], bh);
                        mma16816(ac2[0][2*np+1], A2h[0][kk], bh + 2);
                        mma16816(ac2[1][2*np],   A2h[1][kk], bh);
                        mma16816(ac2[1][2*np+1], A2h[1][kk], bh + 2);
                        mma16816(ac2[0][2*np],   A2h[0][kk], bl);
                        mma16816(ac2[0][2*np+1], A2h[0][kk], bl + 2);
                        mma16816(ac2[1][2*np],   A2h[1][kk], bl);
                        mma16816(ac2[1][2*np+1], A2h[1][kk], bl + 2);
                    }
                }

                float sl[8], ql[8];
                #pragma unroll
                for (int j = 0; j < 8; ++j) { sl[j] = 0.f; ql[j] = 0.f; }
                #pragma unroll
                for (int mt = 0; mt < 2; ++mt) {
                    const int r0 = geBase + R0 + mt * 16 + g;
                    #pragma unroll
                    for (int nt = 0; nt < 4; ++nt) {
                        const int c2 = nt * 4 + cq;
                        float v00 = elu_f(ac2[mt][nt][0]);
                        float v01 = elu_f(ac2[mt][nt][1]);
                        float v10 = elu_f(ac2[mt][nt][2]);
                        float v11 = elu_f(ac2[mt][nt][3]);
                        g_O16[(size_t)(k * 16 + c2) * BE_ + r0]     = packh2(v00, v01);
                        g_O16[(size_t)(k * 16 + c2) * BE_ + r0 + 8] = packh2(v10, v11);
                        sl[nt * 2]     += v00 + v10;
                        ql[nt * 2]     += v00 * v00 + v10 * v10;
                        sl[nt * 2 + 1] += v01 + v11;
                        ql[nt * 2 + 1] += v01 * v01 + v11 * v11;
                    }
                }
                #pragma unroll
                for (int j = 0; j < 8; ++j) {
                    #pragma unroll
                    for (int off = 4; off < 32; off <<= 1) {
                        sl[j] += __shfl_xor_sync(0xffffffffu, sl[j], off);
                        ql[j] += __shfl_xor_sync(0xffffffffu, ql[j], off);
                    }
                }
                if (lid < 4) {
                    #pragma unroll
                    for (int nt = 0; nt < 4; ++nt) {
                        atomicAdd(&SSUM[k * 32 + nt * 8 + 2 * lid],     sl[nt * 2]);
                        atomicAdd(&SSQ [k * 32 + nt * 8 + 2 * lid],     ql[nt * 2]);
                        atomicAdd(&SSUM[k * 32 + nt * 8 + 2 * lid + 1], sl[nt * 2 + 1]);
                        atomicAdd(&SSQ [k * 32 + nt * 8 + 2 * lid + 1], ql[nt * 2 + 1]);
                    }
                }
            }
        }
        __syncthreads();
        if (tid < 64) { atomicAdd(&g_esum[tid], SSUM[tid]); atomicAdd(&g_esq[tid], SSQ[tid]); }
    } else {
        // ================= NODE PATH (2 tiles) =================
        {
            const uint32_t* gv1h = (const uint32_t*)g_wv1h;
            const uint32_t* gv1l = (const uint32_t*)g_wv1l;
            const uint32_t* gv2h = (const uint32_t*)g_wv2h;
            const uint32_t* gv2l = (const uint32_t*)g_wv2l;
            for (int idx = tid; idx < 1024; idx += 128) {   // node W1: [64n][16w]
                int w = idx & 15, n = idx >> 4;
                W1hw[n * 36 + w] = gv1h[idx];
                W1lw[n * 36 + w] = gv1l[idx];
            }
            for (int idx = tid; idx < 2048; idx += 128) {   // node W2: [32n][32w]
                int w = idx & 31, n = idx >> 5;
                W2hw[n * 36 + w] = gv2h[idx];
                W2lw[n * 36 + w] = gv2l[idx];
            }
            if (tid < 64) { SB1[tid] = vb1[tid]; SSUM[tid] = 0.f; SSQ[tid] = 0.f; }
            if (tid < 32) SB2[tid] = vb2[tid];
        }
        __syncthreads();

        const uint32_t w1hk = smb + W1H_B + b4off;
        const uint32_t w1lk = smb + W1L_B + b4off;
        const uint32_t w2hk = smb + W2H_B + b4off;
        const uint32_t w2lk = smb + W2L_B + b4off;

        #pragma unroll 1
        for (int t = 0; t < 2; ++t) {
            const int nb = ((blockIdx.x - 2016) * 2 + t) * 128;

            uint32_t Ah[2][2][4];
            #pragma unroll
            for (int mt = 0; mt < 2; ++mt) {
                #pragma unroll
                for (int kk = 0; kk < 2; ++kk) {
                    const int c0 = kk * 16 + 2 * cq;
                    const float* b0 = g_agg + (size_t)(nb + R0 + mt * 16 + g) * 32;
                    const float* b1 = b0 + 8 * 32;
                    float2 f0 = *(const float2*)(b0 + c0);
                    float2 f1 = *(const float2*)(b1 + c0);
                    float2 f2 = *(const float2*)(b0 + c0 + 8);
                    float2 f3 = *(const float2*)(b1 + c0 + 8);
                    Ah[mt][kk][0] = packh2(f0.x, f0.y);
                    Ah[mt][kk][1] = packh2(f1.x, f1.y);
                    Ah[mt][kk][2] = packh2(f2.x, f2.y);
                    Ah[mt][kk][3] = packh2(f3.x, f3.y);
                }
            }

            float acc[2][8][4];
            #pragma unroll
            for (int nt = 0; nt < 8; ++nt) {
                float bb0 = SB1[nt * 8 + 2 * cq];
                float bb1 = SB1[nt * 8 + 2 * cq + 1];
                acc[0][nt][0] = bb0; acc[0][nt][1] = bb1;
                acc[0][nt][2] = bb0; acc[0][nt][3] = bb1;
                acc[1][nt][0] = bb0; acc[1][nt][1] = bb1;
                acc[1][nt][2] = bb0; acc[1][nt][3] = bb1;
            }
            #pragma unroll
            for (int kk = 0; kk < 2; ++kk) {
                #pragma unroll
                for (int np = 0; np < 4; ++np) {
                    uint32_t bh[4], bl[4];
                    ldsm_x4(w1hk + np * 2304 + kk * 32, bh);
                    ldsm_x4(w1lk + np * 2304 + kk * 32, bl);
                    mma16816(acc[0][2*np],   Ah[0][kk], bh);
                    mma16816(acc[0][2*np+1], Ah[0][kk], bh + 2);
                    mma16816(acc[1][2*np],   Ah[1][kk], bh);
                    mma16816(acc[1][2*np+1], Ah[1][kk], bh + 2);
                    mma16816(acc[0][2*np],   Ah[0][kk], bl);
                    mma16816(acc[0][2*np+1], Ah[0][kk], bl + 2);
                    mma16816(acc[1][2*np],   Ah[1][kk], bl);
                    mma16816(acc[1][2*np+1], Ah[1][kk], bl + 2);
                }
            }

            uint32_t A2h[2][4][4];
            #pragma unroll
            for (int mt = 0; mt < 2; ++mt) {
                #pragma unroll
                for (int kk = 0; kk < 4; ++kk) {
                    float v00 = elu_f(acc[mt][2 * kk][0]);
                    float v01 = elu_f(acc[mt][2 * kk][1]);
                    float v10 = elu_f(acc[mt][2 * kk][2]);
                    float v11 = elu_f(acc[mt][2 * kk][3]);
                    float w00 = elu_f(acc[mt][2 * kk + 1][0]);
                    float w01 = elu_f(acc[mt][2 * kk + 1][1]);
                    float w10 = elu_f(acc[mt][2 * kk + 1][2]);
                    float w11 = elu_f(acc[mt][2 * kk + 1][3]);
                    A2h[mt][kk][0] = packh2(v00, v01);
                    A2h[mt][kk][1] = packh2(v10, v11);
                    A2h[mt][kk][2] = packh2(w00, w01);
                    A2h[mt][kk][3] = packh2(w10, w11);
                }
            }

            float ac2[2][4][4];
            #pragma unroll
            for (int nt = 0; nt < 4; ++nt) {
                float bb0 = SB2[nt * 8 + 2 * cq];
                float bb1 = SB2[nt * 8 + 2 * cq + 1];
                ac2[0][nt][0] = bb0; ac2[0][nt][1] = bb1;
                ac2[0][nt][2] = bb0; ac2[0][nt][3] = bb1;
                ac2[1][nt][0] = bb0; ac2[1][nt][1] = bb1;
                ac2[1][nt][2] = bb0; ac2[1][nt][3] = bb1;
            }
            #pragma unroll
            for (int kk = 0; kk < 4; ++kk) {
                #pragma unroll
                for (int np = 0; np < 2; ++np) {
                    uint32_t bh[4], bl[4];
                    ldsm_x4(w2hk + np * 2304 + kk * 32, bh);
                    ldsm_x4(w2lk + np * 2304 + kk * 32, bl);
                    mma16816(ac2[0][2*np],   A2h[0][kk], bh);
                    mma16816(ac2[0][2*np+1], A2h[0][kk], bh + 2);
                    mma16816(ac2[1][2*np],   A2h[1][kk], bh);
                    mma16816(ac2[1][2*np+1], A2h[1][kk], bh + 2);
                    mma16816(ac2[0][2*np],   A2h[0][kk], bl);
                    mma16816(ac2[0][2*np+1], A2h[0][kk], bl + 2);
                    mma16816(ac2[1][2*np],   A2h[1][kk], bl);
                    mma16816(ac2[1][2*np+1], A2h[1][kk], bl + 2);
                }
            }

            float sl[8], ql[8];
            #pragma unroll
            for (int j = 0; j < 8; ++j) { sl[j] = 0.f; ql[j] = 0.f; }
            #pragma unroll
            for (int mt = 0; mt < 2; ++mt) {
                const int n0 = nb + R0 + mt * 16 + g;
                #pragma unroll
                for (int nt = 0; nt < 4; ++nt) {
                    const int col = nt * 8 + 2 * cq;
                    float v00 = elu_f(ac2[mt][nt][0]);
                    float v01 = elu_f(ac2[mt][nt][1]);
                    float v10 = elu_f(ac2[mt][nt][2]);
                    float v11 = elu_f(ac2[mt][nt][3]);
                    *(float2*)(g_ov + (size_t)n0 * 32 + col)       = make_float2(v00, v01);
                    *(float2*)(g_ov + (size_t)(n0 + 8) * 32 + col) = make_float2(v10, v11);
                    sl[nt * 2]     += v00 + v10;
                    ql[nt * 2]     += v00 * v00 + v10 * v10;
                    sl[nt * 2 + 1] += v01 + v11;
                    ql[nt * 2 + 1] += v01 * v01 + v11 * v11;
                }
            }
            #pragma unroll
            for (int j = 0; j < 8; ++j) {
                #pragma unroll
                for (int off = 4; off < 32; off <<= 1) {
                    sl[j] += __shfl_xor_sync(0xffffffffu, sl[j], off);
                    ql[j] += __shfl_xor_sync(0xffffffffu, ql[j], off);
                }
            }
            if (lid < 4) {
                #pragma unroll
                for (int nt = 0; nt < 4; ++nt) {
                    atomicAdd(&SSUM[nt * 8 + 2 * lid],     sl[nt * 2]);
                    atomicAdd(&SSQ [nt * 8 + 2 * lid],     ql[nt * 2]);
                    atomicAdd(&SSUM[nt * 8 + 2 * lid + 1], sl[nt * 2 + 1]);
                    atomicAdd(&SSQ [nt * 8 + 2 * lid + 1], ql[nt * 2 + 1]);
                }
            }
        }
        __syncthreads();
        if (tid < 32) { atomicAdd(&g_nsum[tid], SSUM[tid]); atomicAdd(&g_nsq[tid], SSQ[tid]); }
    }
}

// ---------------------------------------------------------------------------
// C) fused post-pass: node_norm (blocks 0..1023) | edge_out (1024..3039)
// ---------------------------------------------------------------------------
__global__ __launch_bounds__(256) void postpass(
    const float* __restrict__ et,
    const float* __restrict__ eg, const float* __restrict__ ebet,
    const float* __restrict__ vg, const float* __restrict__ vbet,
    float* __restrict__ dv, float* __restrict__ de)
{
    __shared__ float A[64], C[64];
    const int bx = blockIdx.x, tid = threadIdx.x;

    if (bx < 1024) {
        if (tid < 32) {
            const float inv_cnt = 1.f / 8192.f;
            float mu = g_nsum[tid] * inv_cnt;
            float var = g_nsq[tid] * inv_cnt - mu * mu;
            float a = vg[tid] * rsqrtf(var + 1e-5f);
            A[tid] = a; C[tid] = vbet[tid] - mu * a;
        }
        __syncthreads();
        int idx = bx * 256 + tid;
        int c = idx & 31;
        dv[idx] = g_ov[idx] * A[c] + C[c];
        return;
    }

    if (tid < 64) {
        const float inv_cnt = 1.f / (float)BE_;
        float mu = g_esum[tid] * inv_cnt;
        float var = g_esq[tid] * inv_cnt - mu * mu;
        float a = eg[tid] * rsqrtf(var + 1e-5f);
        A[tid] = a; C[tid] = ebet[tid] - mu * a;
    }
    __syncthreads();

    const int ge = (bx - 1024) * 256 + tid;
    const float2 w = reinterpret_cast<const float2*>(et)[ge];
    float4* dst = (float4*)(de + (size_t)ge * 32);
    #pragma unroll
    for (int i = 0; i < 8; ++i) {
        uint32_t a0 = g_O16[(size_t)(2 * i) * BE_ + ge];
        uint32_t a1 = g_O16[(size_t)(2 * i + 1) * BE_ + ge];
        uint32_t b0 = g_O16[(size_t)(16 + 2 * i) * BE_ + ge];
        uint32_t b1 = g_O16[(size_t)(16 + 2 * i + 1) * BE_ + ge];
        float2 fa0 = __half22float2(*reinterpret_cast<__half2*>(&a0));
        float2 fa1 = __half22float2(*reinterpret_cast<__half2*>(&a1));
        float2 fb0 = __half22float2(*reinterpret_cast<__half2*>(&b0));
        float2 fb1 = __half22float2(*reinterpret_cast<__half2*>(&b1));
        float4 o;
        {
            const int c = 4 * i;
            o.x = (A[c] * fa0.x + C[c]) * w.x + (A[32 + c] * fb0.x + C[32 + c]) * w.y;
        }
        {
            const int c = 4 * i + 1;
            o.y = (A[c] * fa0.y + C[c]) * w.x + (A[32 + c] * fb0.y + C[32 + c]) * w.y;
        }
        {
            const int c = 4 * i + 2;
            o.z = (A[c] * fa1.x + C[c]) * w.x + (A[32 + c] * fb1.x + C[32 + c]) * w.y;
        }
        {
            const int c = 4 * i + 3;
            o.w = (A[c] * fa1.y + C[c]) * w.x + (A[32 + c] * fb1.y + C[32 + c]) * w.y;
        }
        dst[i] = o;
    }
}

// ---------------------------------------------------------------------------
extern "C" void kernel_launch(void* const* d_in, const int* in_sizes, int n_in,
                              void* d_out, int out_size)
{
    const float* v0   = (const float*)d_in[0];
    const float* e0   = (const float*)d_in[1];
    const float* et   = (const float*)d_in[2];
    const float* vW1  = (const float*)d_in[3];
    const float* vb1  = (const float*)d_in[4];
    const float* vW2  = (const float*)d_in[5];
    const float* vb2  = (const float*)d_in[6];
    const float* vg   = (const float*)d_in[7];
    const float* vbet = (const float*)d_in[8];
    const float* eW1  = (const float*)d_in[9];
    const float* eb1  = (const float*)d_in[10];
    const float* eW2  = (const float*)d_in[11];
    const float* eb2  = (const float*)d_in[12];
    const float* eg   = (const float*)d_in[13];
    const float* ebet = (const float*)d_in[14];
    float* out = (float*)d_out;

    cudaFuncSetAttribute(mlp_hmma, cudaFuncAttributeMaxDynamicSharedMemorySize, EH_SMEM);
    cudaFuncSetAttribute(mlp_hmma, cudaFuncAttributePreferredSharedMemoryCarveout, 100);

    prepass<<<5088, 256>>>(e0, eW1, eW2, vW1, vW2, out + ZERO_OFF);
    mlp_hmma<<<2048, 128, EH_SMEM>>>(v0, eb1, eb2, vb1, vb2);
    postpass<<<3040, 256>>>(et, eg, ebet, vg, vbet, out, out + DE_OFF);

    (void)in_sizes; (void)n_in; (void)out_size;
}

// round 14
// speedup vs baseline: 1.6653x; 1.1820x over previous
#include <cuda_runtime.h>
#include <cuda_bf16.h>
#include <cuda_fp16.h>
#include <cstdint>

// ---------------------------------------------------------------------------
// NRI decoder step. Edge+node MLPs on HMMA.
// Single fp16 operands (A and W) -> 1 MMA per GEMM term; fp32 accumulate.
// g_O stored as half2 channel-pairs; 2 tiles per block.
// Shapes: B=128, N=64, K=2, VDIM=EDIM=32, HID=64, E=4032, BE=516096
// Output: [dv (262144) | de (16515072) | zeros (1032192)] floats
// ---------------------------------------------------------------------------

#define BN_  128
#define NN_  64
#define EE_  4032
#define BE_  516096
#define DV_ELEMS   262144
#define ZERO_ELEMS 1032192
#define DE_OFF     262144
#define ZERO_OFF   16777216

// scratch (device globals; no runtime allocation)
__device__ uint32_t g_O16[(size_t)32 * BE_]; // edge outputs half2 [(k*16+cp)][ge]
__device__ float g_agg[BN_ * NN_ * 32];
__device__ float g_ov[BN_ * NN_ * 32];       // node MLP outputs [node][32]
__device__ float g_esum[64], g_esq[64];
__device__ float g_nsum[32], g_nsq[32];
// pre-transposed fp16 weights (B-operand layout, k contiguous)
__device__ __half g_w1h[8192];   // edge W1 [2][64 n][64 f]
__device__ __half g_w2h[4096];   // edge W2 [2][32 n][64 h]
__device__ __half g_wv1h[2048];  // node W1 [64 n][32 f]
__device__ __half g_wv2h[2048];  // node W2 [32 n][64 h]

__device__ __forceinline__ float elu_f(float x) {
    return x > 0.f ? x : (__expf(x) - 1.f);
}
__device__ __forceinline__ uint32_t smem_u32(const void* p) {
    uint32_t a;
    asm("{ .reg .u64 t; cvta.to.shared.u64 t, %1; cvt.u32.u64 %0, t; }" : "=r"(a) : "l"(p));
    return a;
}
__device__ __forceinline__ uint32_t packh2(float lo, float hi) {
    uint32_t r;
    asm("cvt.rn.f16x2.f32 %0, %1, %2;" : "=r"(r) : "f"(hi), "f"(lo));
    return r;
}

// ---- warp MMA helpers (fp16 inputs, fp32 accum) ---------------------------
__device__ __forceinline__ void ldsm_x4(uint32_t addr, uint32_t r[4]) {
    asm volatile("ldmatrix.sync.aligned.m8n8.x4.shared.b16 {%0,%1,%2,%3}, [%4];"
        : "=r"(r[0]), "=r"(r[1]), "=r"(r[2]), "=r"(r[3]) : "r"(addr));
}
__device__ __forceinline__ void mma16816(float c[4], const uint32_t a[4], const uint32_t b[2]) {
    asm volatile("mma.sync.aligned.m16n8k16.row.col.f32.f16.f16.f32 "
        "{%0,%1,%2,%3}, {%4,%5,%6,%7}, {%8,%9}, {%0,%1,%2,%3};"
        : "+f"(c[0]), "+f"(c[1]), "+f"(c[2]), "+f"(c[3])
        : "r"(a[0]), "r"(a[1]), "r"(a[2]), "r"(a[3]), "r"(b[0]), "r"(b[1]));
}

// ---------------------------------------------------------------------------
// A) fused pre-pass: zeros+stats | weight prep (fp16) | aggregation
// ---------------------------------------------------------------------------
__global__ __launch_bounds__(256) void prepass(
    const float* __restrict__ e0,
    const float* __restrict__ w1, const float* __restrict__ w2,
    const float* __restrict__ vw1, const float* __restrict__ vw2,
    float* __restrict__ zout)
{
    const int bx = blockIdx.x, tid = threadIdx.x;
    if (bx < 4032) {
        int idx = bx * 256 + tid;
        zout[idx] = 0.f;
        if (bx == 0) {
            if (tid < 64) { g_esum[tid] = 0.f; g_esq[tid] = 0.f; }
            else if (tid < 96) { g_nsum[tid - 64] = 0.f; g_nsq[tid - 64] = 0.f; }
        }
        return;
    }
    if (bx < 4064) {
        int t = (bx - 4032) * 256 + tid;        // 8192 threads
        {   // edge w1: t = (k*64+n)*64+f  <-  w1[(k*64+f)*64+n]
            int f = t & 63, n = (t >> 6) & 63, k = t >> 12;
            g_w1h[t] = __float2half(w1[(k * 64 + f) * 64 + n]);
        }
        if (t < 4096) {  // edge w2: t = (k*32+n)*64+h  <-  w2[(k*64+h)*32+n]
            int hh = t & 63, n = (t >> 6) & 31, k = t >> 11;
            g_w2h[t] = __float2half(w2[(k * 64 + hh) * 32 + n]);
        }
        if (t < 2048) {  // node w1: t = n*32+f  <-  vw1[f*64+n]
            int f = t & 31, n = t >> 5;
            g_wv1h[t] = __float2half(vw1[f * 64 + n]);
        }
        if (t < 2048) {  // node w2: t = n*64+h  <-  vw2[h*32+n]
            int hh = t & 63, n = t >> 6;
            g_wv2h[t] = __float2half(vw2[hh * 32 + n]);
        }
        return;
    }
    {   // edge2node aggregation
        int gw = ((bx - 4064) * 256 + tid) >> 5;
        int lane = tid & 31;
        int b = gw >> 6, j = gw & 63;
        const float* base = e0 + (size_t)b * (NN_ * 63 * 32) + lane;
        float acc = 0.f;
        #pragma unroll 4
        for (int i = 0; i < 64; ++i) {
            if (i == j) continue;
            int jj = (j < i) ? j : j - 1;
            acc += base[(i * 63 + jj) * 32];
        }
        g_agg[gw * 32 + lane] = acc * (1.f / 64.f);
    }
}

// ---------------------------------------------------------------------------
// B) unified HMMA kernel, 2 tiles per block.
//    blocks 0..2015 edge (tiles 2bx, 2bx+1), 2016..2047 node (2 tiles each)
// smem (bytes):
//   0      W1h [2k][64 n][72 b16]   18432
//   18432  W2h [2k][32 n][72]        9216
//   27648  CTRL: SB1[128] SB2[64] SSUM[64] SSQ[64]  1280
// ---------------------------------------------------------------------------
#define W1H_B  0
#define W2H_B  18432
#define CTRL_B 27648
#define EH_SMEM 28928

__global__ __launch_bounds__(128, 3) void mlp_hmma(
    const float* __restrict__ v0,
    const float* __restrict__ eb1, const float* __restrict__ eb2,
    const float* __restrict__ vb1, const float* __restrict__ vb2)
{
    extern __shared__ char sm[];
    const uint32_t smb = smem_u32(sm);
    const int tid = threadIdx.x, wid = tid >> 5, lid = tid & 31;
    const int R0 = wid * 32;

    float* SB1  = (float*)(sm + CTRL_B);
    float* SB2  = (float*)(sm + CTRL_B + 512);
    float* SSUM = (float*)(sm + CTRL_B + 768);
    float* SSQ  = (float*)(sm + CTRL_B + 1024);

    const int b4off = (lid & 7) * 144 + ((lid >> 3) & 1) * 16 + ((lid >> 4) & 1) * 1152;
    const int g  = lid >> 2;
    const int cq = lid & 3;

    uint4* W1h4 = (uint4*)(sm + W1H_B);
    uint4* W2h4 = (uint4*)(sm + W2H_B);

    if (blockIdx.x < 2016) {
        // ================= EDGE PATH (2 tiles) =================
        {
            const uint4* gw1 = (const uint4*)g_w1h;   // 1024 uint4 (128 rows x 8)
            const uint4* gw2 = (const uint4*)g_w2h;   // 512 uint4 (64 rows x 8)
            for (int i4 = tid; i4 < 1024; i4 += 128) {
                int row = i4 >> 3, w4 = (i4 & 7) << 2;
                W1h4[(row * 36 + w4) >> 2] = gw1[i4];
            }
            for (int i4 = tid; i4 < 512; i4 += 128) {
                int row = i4 >> 3, w4 = (i4 & 7) << 2;
                W2h4[(row * 36 + w4) >> 2] = gw2[i4];
            }
            if (tid < 128) SB1[tid] = eb1[tid];
            if (tid < 64)  { SB2[tid] = eb2[tid]; SSUM[tid] = 0.f; SSQ[tid] = 0.f; }
        }
        __syncthreads();

        const uint32_t bW1h4 = smb + W1H_B + b4off;
        const uint32_t bW2h4 = smb + W2H_B + b4off;

        #pragma unroll 1
        for (int t = 0; t < 2; ++t) {
            const int tileIdx = blockIdx.x * 2 + t;
            const int geT = tileIdx * 128 + R0;
            int offR[4], offS[4];
            #pragma unroll
            for (int m2 = 0; m2 < 4; ++m2) {
                int mt = m2 >> 1, rs = (m2 & 1) * 8;
                int gid = geT + mt * 16 + g + rs;
                int b = gid / EE_;
                int e = gid - b * EE_;
                int i0 = e / 63, jj = e - i0 * 63;
                int rc = (jj < i0) ? jj : jj + 1;
                offR[m2] = (b * 64 + rc) * 32;
                offS[m2] = (b * 64 + i0) * 32;
            }

            // gather A fragments (fp16)
            uint32_t Ah[2][4][4];
            #pragma unroll
            for (int mt = 0; mt < 2; ++mt) {
                #pragma unroll
                for (int kk = 0; kk < 4; ++kk) {
                    const int c0 = (kk & 1) * 16 + 2 * cq;
                    const float* b0 = v0 + ((kk < 2) ? offR[mt * 2]     : offS[mt * 2]);
                    const float* b1 = v0 + ((kk < 2) ? offR[mt * 2 + 1] : offS[mt * 2 + 1]);
                    float2 f0 = *(const float2*)(b0 + c0);
                    float2 f1 = *(const float2*)(b1 + c0);
                    float2 f2 = *(const float2*)(b0 + c0 + 8);
                    float2 f3 = *(const float2*)(b1 + c0 + 8);
                    Ah[mt][kk][0] = packh2(f0.x, f0.y);
                    Ah[mt][kk][1] = packh2(f1.x, f1.y);
                    Ah[mt][kk][2] = packh2(f2.x, f2.y);
                    Ah[mt][kk][3] = packh2(f3.x, f3.y);
                }
            }

            const int geBase = tileIdx * 128;

            #pragma unroll 1
            for (int k = 0; k < 2; ++k) {
                const float* SB1k = SB1 + k * 64;
                const float* SB2k = SB2 + k * 32;
                const uint32_t w1hk = bW1h4 + k * 9216;
                const uint32_t w2hk = bW2h4 + k * 4608;

                float acc[2][8][4];
                #pragma unroll
                for (int nt = 0; nt < 8; ++nt) {
                    float bb0 = SB1k[nt * 8 + 2 * cq];
                    float bb1 = SB1k[nt * 8 + 2 * cq + 1];
                    acc[0][nt][0] = bb0; acc[0][nt][1] = bb1;
                    acc[0][nt][2] = bb0; acc[0][nt][3] = bb1;
                    acc[1][nt][0] = bb0; acc[1][nt][1] = bb1;
                    acc[1][nt][2] = bb0; acc[1][nt][3] = bb1;
                }
                #pragma unroll
                for (int kk = 0; kk < 4; ++kk) {
                    #pragma unroll
                    for (int np = 0; np < 4; ++np) {
                        uint32_t bh[4];
                        ldsm_x4(w1hk + np * 2304 + kk * 32, bh);
                        mma16816(acc[0][2*np],   Ah[0][kk], bh);
                        mma16816(acc[0][2*np+1], Ah[0][kk], bh + 2);
                        mma16816(acc[1][2*np],   Ah[1][kk], bh);
                        mma16816(acc[1][2*np+1], Ah[1][kk], bh + 2);
                    }
                }

                // epilogue 1: ELU, pack fp16 A2 fragments
                uint32_t A2h[2][4][4];
                #pragma unroll
                for (int mt = 0; mt < 2; ++mt) {
                    #pragma unroll
                    for (int kk = 0; kk < 4; ++kk) {
                        float v00 = elu_f(acc[mt][2 * kk][0]);
                        float v01 = elu_f(acc[mt][2 * kk][1]);
                        float v10 = elu_f(acc[mt][2 * kk][2]);
                        float v11 = elu_f(acc[mt][2 * kk][3]);
                        float w00 = elu_f(acc[mt][2 * kk + 1][0]);
                        float w01 = elu_f(acc[mt][2 * kk + 1][1]);
                        float w10 = elu_f(acc[mt][2 * kk + 1][2]);
                        float w11 = elu_f(acc[mt][2 * kk + 1][3]);
                        A2h[mt][kk][0] = packh2(v00, v01);
                        A2h[mt][kk][1] = packh2(v10, v11);
                        A2h[mt][kk][2] = packh2(w00, w01);
                        A2h[mt][kk][3] = packh2(w10, w11);
                    }
                }

                float ac2[2][4][4];
                #pragma unroll
                for (int nt = 0; nt < 4; ++nt) {
                    float bb0 = SB2k[nt * 8 + 2 * cq];
                    float bb1 = SB2k[nt * 8 + 2 * cq + 1];
                    ac2[0][nt][0] = bb0; ac2[0][nt][1] = bb1;
                    ac2[0][nt][2] = bb0; ac2[0][nt][3] = bb1;
                    ac2[1][nt][0] = bb0; ac2[1][nt][1] = bb1;
                    ac2[1][nt][2] = bb0; ac2[1][nt][3] = bb1;
                }
                #pragma unroll
                for (int kk = 0; kk < 4; ++kk) {
                    #pragma unroll
                    for (int np = 0; np < 2; ++np) {
                        uint32_t bh[4];
                        ldsm_x4(w2hk + np * 2304 + kk * 32, bh);
                        mma16816(ac2[0][2*np],   A2h[0][kk], bh);
                        mma16816(ac2[0][2*np+1], A2h[0][kk], bh + 2);
                        mma16816(ac2[1][2*np],   A2h[1][kk], bh);
                        mma16816(ac2[1][2*np+1], A2h[1][kk], bh + 2);
                    }
                }

                float sl[8], ql[8];
                #pragma unroll
                for (int j = 0; j < 8; ++j) { sl[j] = 0.f; ql[j] = 0.f; }
                #pragma unroll
                for (int mt = 0; mt < 2; ++mt) {
                    const int r0 = geBase + R0 + mt * 16 + g;
                    #pragma unroll
                    for (int nt = 0; nt < 4; ++nt) {
                        const int c2 = nt * 4 + cq;
                        float v00 = elu_f(ac2[mt][nt][0]);
                        float v01 = elu_f(ac2[mt][nt][1]);
                        float v10 = elu_f(ac2[mt][nt][2]);
                        float v11 = elu_f(ac2[mt][nt][3]);
                        g_O16[(size_t)(k * 16 + c2) * BE_ + r0]     = packh2(v00, v01);
                        g_O16[(size_t)(k * 16 + c2) * BE_ + r0 + 8] = packh2(v10, v11);
                        sl[nt * 2]     += v00 + v10;
                        ql[nt * 2]     += v00 * v00 + v10 * v10;
                        sl[nt * 2 + 1] += v01 + v11;
                        ql[nt * 2 + 1] += v01 * v01 + v11 * v11;
                    }
                }
                #pragma unroll
                for (int j = 0; j < 8; ++j) {
                    #pragma unroll
                    for (int off = 4; off < 32; off <<= 1) {
                        sl[j] += __shfl_xor_sync(0xffffffffu, sl[j], off);
                        ql[j] += __shfl_xor_sync(0xffffffffu, ql[j], off);
                    }
                }
                if (lid < 4) {
                    #pragma unroll
                    for (int nt = 0; nt < 4; ++nt) {
                        atomicAdd(&SSUM[k * 32 + nt * 8 + 2 * lid],     sl[nt * 2]);
                        atomicAdd(&SSQ [k * 32 + nt * 8 + 2 * lid],     ql[nt * 2]);
                        atomicAdd(&SSUM[k * 32 + nt * 8 + 2 * lid + 1], sl[nt * 2 + 1]);
                        atomicAdd(&SSQ [k * 32 + nt * 8 + 2 * lid + 1], ql[nt * 2 + 1]);
                    }
                }
            }
        }
        __syncthreads();
        if (tid < 64) { atomicAdd(&g_esum[tid], SSUM[tid]); atomicAdd(&g_esq[tid], SSQ[tid]); }
    } else {
        // ================= NODE PATH (2 tiles) =================
        {
            const uint4* gv1 = (const uint4*)g_wv1h;   // 64 rows x 4 uint4
            const uint4* gv2 = (const uint4*)g_wv2h;   // 32 rows x 8 uint4
            for (int i4 = tid; i4 < 256; i4 += 128) {
                int row = i4 >> 2, w4 = (i4 & 3) << 2;
                W1h4[(row * 36 + w4) >> 2] = gv1[i4];
            }
            for (int i4 = tid; i4 < 256; i4 += 128) {
                int row = i4 >> 3, w4 = (i4 & 7) << 2;
                W2h4[(row * 36 + w4) >> 2] = gv2[i4];
            }
            if (tid < 64) { SB1[tid] = vb1[tid]; SSUM[tid] = 0.f; SSQ[tid] = 0.f; }
            if (tid < 32) SB2[tid] = vb2[tid];
        }
        __syncthreads();

        const uint32_t w1hk = smb + W1H_B + b4off;
        const uint32_t w2hk = smb + W2H_B + b4off;

        #pragma unroll 1
        for (int t = 0; t < 2; ++t) {
            const int nb = ((blockIdx.x - 2016) * 2 + t) * 128;

            uint32_t Ah[2][2][4];
            #pragma unroll
            for (int mt = 0; mt < 2; ++mt) {
                #pragma unroll
                for (int kk = 0; kk < 2; ++kk) {
                    const int c0 = kk * 16 + 2 * cq;
                    const float* b0 = g_agg + (size_t)(nb + R0 + mt * 16 + g) * 32;
                    const float* b1 = b0 + 8 * 32;
                    float2 f0 = *(const float2*)(b0 + c0);
                    float2 f1 = *(const float2*)(b1 + c0);
                    float2 f2 = *(const float2*)(b0 + c0 + 8);
                    float2 f3 = *(const float2*)(b1 + c0 + 8);
                    Ah[mt][kk][0] = packh2(f0.x, f0.y);
                    Ah[mt][kk][1] = packh2(f1.x, f1.y);
                    Ah[mt][kk][2] = packh2(f2.x, f2.y);
                    Ah[mt][kk][3] = packh2(f3.x, f3.y);
                }
            }

            float acc[2][8][4];
            #pragma unroll
            for (int nt = 0; nt < 8; ++nt) {
                float bb0 = SB1[nt * 8 + 2 * cq];
                float bb1 = SB1[nt * 8 + 2 * cq + 1];
                acc[0][nt][0] = bb0; acc[0][nt][1] = bb1;
                acc[0][nt][2] = bb0; acc[0][nt][3] = bb1;
                acc[1][nt][0] = bb0; acc[1][nt][1] = bb1;
                acc[1][nt][2] = bb0; acc[1][nt][3] = bb1;
            }
            #pragma unroll
            for (int kk = 0; kk < 2; ++kk) {
                #pragma unroll
                for (int np = 0; np < 4; ++np) {
                    uint32_t bh[4];
                    ldsm_x4(w1hk + np * 2304 + kk * 32, bh);
                    mma16816(acc[0][2*np],   Ah[0][kk], bh);
                    mma16816(acc[0][2*np+1], Ah[0][kk], bh + 2);
                    mma16816(acc[1][2*np],   Ah[1][kk], bh);
                    mma16816(acc[1][2*np+1], Ah[1][kk], bh + 2);
                }
            }

            uint32_t A2h[2][4][4];
            #pragma unroll
            for (int mt = 0; mt < 2; ++mt) {
                #pragma unroll
                for (int kk = 0; kk < 4; ++kk) {
                    float v00 = elu_f(acc[mt][2 * kk][0]);
                    float v01 = elu_f(acc[mt][2 * kk][1]);
                    float v10 = elu_f(acc[mt][2 * kk][2]);
                    float v11 = elu_f(acc[mt][2 * kk][3]);
                    float w00 = elu_f(acc[mt][2 * kk + 1][0]);
                    float w01 = elu_f(acc[mt][2 * kk + 1][1]);
                    float w10 = elu_f(acc[mt][2 * kk + 1][2]);
                    float w11 = elu_f(acc[mt][2 * kk + 1][3]);
                    A2h[mt][kk][0] = packh2(v00, v01);
                    A2h[mt][kk][1] = packh2(v10, v11);
                    A2h[mt][kk][2] = packh2(w00, w01);
                    A2h[mt][kk][3] = packh2(w10, w11);
                }
            }

            float ac2[2][4][4];
            #pragma unroll
            for (int nt = 0; nt < 4; ++nt) {
                float bb0 = SB2[nt * 8 + 2 * cq];
                float bb1 = SB2[nt * 8 + 2 * cq + 1];
                ac2[0][nt][0] = bb0; ac2[0][nt][1] = bb1;
                ac2[0][nt][2] = bb0; ac2[0][nt][3] = bb1;
                ac2[1][nt][0] = bb0; ac2[1][nt][1] = bb1;
                ac2[1][nt][2] = bb0; ac2[1][nt][3] = bb1;
            }
            #pragma unroll
            for (int kk = 0; kk < 4; ++kk) {
                #pragma unroll
                for (int np = 0; np < 2; ++np) {
                    uint32_t bh[4];
                    ldsm_x4(w2hk + np * 2304 + kk * 32, bh);
                    mma16816(ac2[0][2*np],   A2h[0][kk], bh);
                    mma16816(ac2[0][2*np+1], A2h[0][kk], bh + 2);
                    mma16816(ac2[1][2*np],   A2h[1][kk], bh);
                    mma16816(ac2[1][2*np+1], A2h[1][kk], bh + 2);
                }
            }

            float sl[8], ql[8];
            #pragma unroll
            for (int j = 0; j < 8; ++j) { sl[j] = 0.f; ql[j] = 0.f; }
            #pragma unroll
            for (int mt = 0; mt < 2; ++mt) {
                const int n0 = nb + R0 + mt * 16 + g;
                #pragma unroll
                for (int nt = 0; nt < 4; ++nt) {
                    const int col = nt * 8 + 2 * cq;
                    float v00 = elu_f(ac2[mt][nt][0]);
                    float v01 = elu_f(ac2[mt][nt][1]);
                    float v10 = elu_f(ac2[mt][nt][2]);
                    float v11 = elu_f(ac2[mt][nt][3]);
                    *(float2*)(g_ov + (size_t)n0 * 32 + col)       = make_float2(v00, v01);
                    *(float2*)(g_ov + (size_t)(n0 + 8) * 32 + col) = make_float2(v10, v11);
                    sl[nt * 2]     += v00 + v10;
                    ql[nt * 2]     += v00 * v00 + v10 * v10;
                    sl[nt * 2 + 1] += v01 + v11;
                    ql[nt * 2 + 1] += v01 * v01 + v11 * v11;
                }
            }
            #pragma unroll
            for (int j = 0; j < 8; ++j) {
                #pragma unroll
                for (int off = 4; off < 32; off <<= 1) {
                    sl[j] += __shfl_xor_sync(0xffffffffu, sl[j], off);
                    ql[j] += __shfl_xor_sync(0xffffffffu, ql[j], off);
                }
            }
            if (lid < 4) {
                #pragma unroll
                for (int nt = 0; nt < 4; ++nt) {
                    atomicAdd(&SSUM[nt * 8 + 2 * lid],     sl[nt * 2]);
                    atomicAdd(&SSQ [nt * 8 + 2 * lid],     ql[nt * 2]);
                    atomicAdd(&SSUM[nt * 8 + 2 * lid + 1], sl[nt * 2 + 1]);
                    atomicAdd(&SSQ [nt * 8 + 2 * lid + 1], ql[nt * 2 + 1]);
                }
            }
        }
        __syncthreads();
        if (tid < 32) { atomicAdd(&g_nsum[tid], SSUM[tid]); atomicAdd(&g_nsq[tid], SSQ[tid]); }
    }
}

// ---------------------------------------------------------------------------
// C) fused post-pass: node_norm (blocks 0..1023) | edge_out (1024..3039)
// ---------------------------------------------------------------------------
__global__ __launch_bounds__(256) void postpass(
    const float* __restrict__ et,
    const float* __restrict__ eg, const float* __restrict__ ebet,
    const float* __restrict__ vg, const float* __restrict__ vbet,
    float* __restrict__ dv, float* __restrict__ de)
{
    __shared__ float A[64], C[64];
    const int bx = blockIdx.x, tid = threadIdx.x;

    if (bx < 1024) {
        if (tid < 32) {
            const float inv_cnt = 1.f / 8192.f;
            float mu = g_nsum[tid] * inv_cnt;
            float var = g_nsq[tid] * inv_cnt - mu * mu;
            float a = vg[tid] * rsqrtf(var + 1e-5f);
            A[tid] = a; C[tid] = vbet[tid] - mu * a;
        }
        __syncthreads();
        int idx = bx * 256 + tid;
        int c = idx & 31;
        dv[idx] = g_ov[idx] * A[c] + C[c];
        return;
    }

    if (tid < 64) {
        const float inv_cnt = 1.f / (float)BE_;
        float mu = g_esum[tid] * inv_cnt;
        float var = g_esq[tid] * inv_cnt - mu * mu;
        float a = eg[tid] * rsqrtf(var + 1e-5f);
        A[tid] = a; C[tid] = ebet[tid] - mu * a;
    }
    __syncthreads();

    const int ge = (bx - 1024) * 256 + tid;
    const float2 w = reinterpret_cast<const float2*>(et)[ge];
    float4* dst = (float4*)(de + (size_t)ge * 32);
    #pragma unroll
    for (int i = 0; i < 8; ++i) {
        uint32_t a0 = g_O16[(size_t)(2 * i) * BE_ + ge];
        uint32_t a1 = g_O16[(size_t)(2 * i + 1) * BE_ + ge];
        uint32_t b0 = g_O16[(size_t)(16 + 2 * i) * BE_ + ge];
        uint32_t b1 = g_O16[(size_t)(16 + 2 * i + 1) * BE_ + ge];
        float2 fa0 = __half22float2(*reinterpret_cast<__half2*>(&a0));
        float2 fa1 = __half22float2(*reinterpret_cast<__half2*>(&a1));
        float2 fb0 = __half22float2(*reinterpret_cast<__half2*>(&b0));
        float2 fb1 = __half22float2(*reinterpret_cast<__half2*>(&b1));
        float4 o;
        {
            const int c = 4 * i;
            o.x = (A[c] * fa0.x + C[c]) * w.x + (A[32 + c] * fb0.x + C[32 + c]) * w.y;
        }
        {
            const int c = 4 * i + 1;
            o.y = (A[c] * fa0.y + C[c]) * w.x + (A[32 + c] * fb0.y + C[32 + c]) * w.y;
        }
        {
            const int c = 4 * i + 2;
            o.z = (A[c] * fa1.x + C[c]) * w.x + (A[32 + c] * fb1.x + C[32 + c]) * w.y;
        }
        {
            const int c = 4 * i + 3;
            o.w = (A[c] * fa1.y + C[c]) * w.x + (A[32 + c] * fb1.y + C[32 + c]) * w.y;
        }
        dst[i] = o;
    }
}

// ---------------------------------------------------------------------------
extern "C" void kernel_launch(void* const* d_in, const int* in_sizes, int n_in,
                              void* d_out, int out_size)
{
    const float* v0   = (const float*)d_in[0];
    const float* e0   = (const float*)d_in[1];
    const float* et   = (const float*)d_in[2];
    const float* vW1  = (const float*)d_in[3];
    const float* vb1  = (const float*)d_in[4];
    const float* vW2  = (const float*)d_in[5];
    const float* vb2  = (const float*)d_in[6];
    const float* vg   = (const float*)d_in[7];
    const float* vbet = (const float*)d_in[8];
    const float* eW1  = (const float*)d_in[9];
    const float* eb1  = (const float*)d_in[10];
    const float* eW2  = (const float*)d_in[11];
    const float* eb2  = (const float*)d_in[12];
    const float* eg   = (const float*)d_in[13];
    const float* ebet = (const float*)d_in[14];
    float* out = (float*)d_out;

    cudaFuncSetAttribute(mlp_hmma, cudaFuncAttributeMaxDynamicSharedMemorySize, EH_SMEM);
    cudaFuncSetAttribute(mlp_hmma, cudaFuncAttributePreferredSharedMemoryCarveout, 100);

    prepass<<<5088, 256>>>(e0, eW1, eW2, vW1, vW2, out + ZERO_OFF);
    mlp_hmma<<<2048, 128, EH_SMEM>>>(v0, eb1, eb2, vb1, vb2);
    postpass<<<3040, 256>>>(et, eg, ebet, vg, vbet, out, out + DE_OFF);

    (void)in_sizes; (void)n_in; (void)out_size;
}